// round 12
// baseline (speedup 1.0000x reference)
#include <cuda_runtime.h>
#include <cuda_fp16.h>
#include <cstdint>

// ---------------------------------------------------------------------------
// Problem constants
// ---------------------------------------------------------------------------
#define MAX_NODES 50000
#define MAX_EDGES 800000
#define NODE_DIM  64
#define GNN_H     128
#define GNN_DIM   64
#define NB        128
#define HIDDEN    256
#define ACTION_DIM 8
#define SCAN_BLK  1024
#define SBLOCKS_MAX ((MAX_NODES + SCAN_BLK - 1) / SCAN_BLK)

// ---------------------------------------------------------------------------
// Device scratch
// ---------------------------------------------------------------------------
__device__ __half  g_bufXh[MAX_NODES * NODE_DIM];
__device__ __half  g_bufPh[MAX_NODES * GNN_H];
__device__ uint8_t g_bufQ8[MAX_NODES * GNN_H];   // e4m3 Q tables
__device__ __half  g_bufSh[MAX_NODES * GNN_H];
__device__ int     g_deg[MAX_NODES];
__device__ int     g_cursor[MAX_NODES];
__device__ int     g_rowptr[MAX_NODES];
__device__ int     g_csr[MAX_EDGES];
__device__ int     g_agg[SBLOCKS_MAX];
__device__ int     g_flag[SBLOCKS_MAX];
__device__ float   g_gsum[NB * GNN_DIM];
__device__ int     g_gcnt[NB];

// ---------------------------------------------------------------------------
// fp8 conversion helpers (e4m3)
// ---------------------------------------------------------------------------
__device__ __forceinline__ __half2 e4m3x2_to_h2(uint16_t v)
{
    uint32_t r;
    asm("cvt.rn.f16x2.e4m3x2 %0, %1;" : "=r"(r) : "h"(v));
    return *(__half2*)&r;
}

// packs: high byte = hi, low byte = lo
__device__ __forceinline__ uint16_t f32x2_to_e4m3x2(float hi, float lo)
{
    uint16_t r;
    asm("cvt.rn.satfinite.e4m3x2.f32 %0, %1, %2;" : "=h"(r) : "f"(hi), "f"(lo));
    return r;
}

// ---------------------------------------------------------------------------
// zero (main stream, pre-fork)
// ---------------------------------------------------------------------------
__global__ void zero_side_kernel(int* __restrict__ deg, int* __restrict__ gcnt,
                                 int* __restrict__ flag, int n_nodes, int n_graphs)
{
    int i = blockIdx.x * blockDim.x + threadIdx.x;
    if (i < n_nodes) deg[i] = 0;
    if (i < n_graphs) gcnt[i] = 0;
    if (i < SBLOCKS_MAX) flag[i] = 0;
}

__global__ void hist_count4_kernel(const int* __restrict__ dst, int* __restrict__ deg,
                                   const int* __restrict__ nb, int* __restrict__ gcnt,
                                   int n_edges, int n_nodes)
{
    int t = blockIdx.x * blockDim.x + threadIdx.x;
    int base = t * 4;
    if (base + 3 < n_edges) {
        int4 d = *(const int4*)(dst + base);
        atomicAdd(&deg[d.x], 1);
        atomicAdd(&deg[d.y], 1);
        atomicAdd(&deg[d.z], 1);
        atomicAdd(&deg[d.w], 1);
    } else {
        for (int i = base; i < n_edges; i++) atomicAdd(&deg[dst[i]], 1);
    }
    if (base + 3 < n_nodes) {
        int4 b = *(const int4*)(nb + base);
        atomicAdd(&gcnt[b.x], 1);
        atomicAdd(&gcnt[b.y], 1);
        atomicAdd(&gcnt[b.z], 1);
        atomicAdd(&gcnt[b.w], 1);
    } else if (base < n_nodes) {
        for (int i = base; i < n_nodes; i++) atomicAdd(&gcnt[nb[i]], 1);
    }
}

// Single-kernel scan: block-local Hillis-Steele + warp-parallel lookback.
__global__ __launch_bounds__(SCAN_BLK) void scan_lb_kernel(
    const int* __restrict__ deg, int* __restrict__ rowptr, int* __restrict__ cursor,
    int* __restrict__ agg, int* __restrict__ flag, int n)
{
    __shared__ int sm[SCAN_BLK];
    __shared__ int s_run;
    int t = threadIdx.x, b = blockIdx.x;
    int i = b * SCAN_BLK + t;
    int v = (i < n) ? deg[i] : 0;
    sm[t] = v;
    __syncthreads();
    #pragma unroll
    for (int off = 1; off < SCAN_BLK; off <<= 1) {
        int u = (t >= off) ? sm[t - off] : 0;
        __syncthreads();
        sm[t] += u;
        __syncthreads();
    }
    if (t == 0) {
        agg[b] = sm[SCAN_BLK - 1];
        __threadfence();
        atomicExch(&flag[b], 1);
    }
    if (t < 32) {
        int run = 0;
        for (int j = t; j < b; j += 32) {
            while (atomicAdd(&flag[j], 0) == 0) { }
            __threadfence();
            run += *(volatile const int*)&agg[j];
        }
        #pragma unroll
        for (int off = 16; off; off >>= 1)
            run += __shfl_down_sync(0xffffffffu, run, off);
        if (t == 0) s_run = run;
    }
    __syncthreads();
    if (i < n) {
        int r = s_run + sm[t] - v;   // exclusive
        rowptr[i] = r;
        cursor[i] = r;
    }
}

__global__ void fill_kernel(const int* __restrict__ src, const int* __restrict__ dst,
                            int* __restrict__ cursor, int* __restrict__ csr, int n_edges)
{
    int e = blockIdx.x * blockDim.x + threadIdx.x;
    if (e >= n_edges) return;
    int pos = atomicAdd(&cursor[dst[e]], 1);
    csr[pos] = src[e];
}

// ---------------------------------------------------------------------------
// Main-stream init: convert x to fp16 + zero gsum
// ---------------------------------------------------------------------------
__global__ void init_main_kernel(const float* __restrict__ x, __half* __restrict__ xh,
                                 float* __restrict__ gsum, int n_graphs, int ncvt)
{
    int i = blockIdx.x * blockDim.x + threadIdx.x;
    if (i < ncvt) {
        float4 v = ((const float4*)x)[i];
        uint2 o;
        *(__half2*)&o.x = __floats2half2_rn(v.x, v.y);
        *(__half2*)&o.y = __floats2half2_rn(v.z, v.w);
        ((uint2*)xh)[i] = o;
    }
    if (i < n_graphs * GNN_DIM) gsum[i] = 0.f;
}

// ---------------------------------------------------------------------------
// MMA machinery
// ---------------------------------------------------------------------------
struct MmaCtx { int tid, g, ti, warp_m, warp_n; };

__device__ __forceinline__ MmaCtx make_ctx()
{
    MmaCtx c;
    c.tid = threadIdx.x;
    int lane = c.tid & 31;
    int wid  = c.tid >> 5;
    c.g = lane >> 2;
    c.ti = lane & 3;
    c.warp_m = wid & 3;
    c.warp_n = wid >> 2;
    return c;
}

__device__ __forceinline__ void mma16(float c[4], const uint32_t a[4], const uint32_t b[2])
{
    asm volatile(
        "mma.sync.aligned.m16n8k16.row.col.f32.f16.f16.f32 "
        "{%0,%1,%2,%3}, {%4,%5,%6,%7}, {%8,%9}, {%0,%1,%2,%3};"
        : "+f"(c[0]), "+f"(c[1]), "+f"(c[2]), "+f"(c[3])
        : "r"(a[0]), "r"(a[1]), "r"(a[2]), "r"(a[3]), "r"(b[0]), "r"(b[1]));
}

// ---------------------------------------------------------------------------
// Full-K single-sync GEMM core for K=64 (lda = 64 halves)
// ---------------------------------------------------------------------------
__device__ __forceinline__ void gemm_fullk64(
    const __half* __restrict__ A, const float* __restrict__ W,
    int M, int ldw, int bm, int bn,
    uint32_t (&As)[128][36], uint32_t (&Bs)[64][36],
    const MmaCtx& c, float acc[2][4][4])
{
    {
        int row   = c.tid >> 1;
        int cbase = (c.tid & 1) * 4;
        bool ok = (bm + row) < M;
        const __half* ap = A + (size_t)(bm + row) * 64;
        #pragma unroll
        for (int cc = 0; cc < 4; cc++) {
            int cu = cbase + cc;
            uint4 v = make_uint4(0u, 0u, 0u, 0u);
            if (ok) v = *(const uint4*)(ap + cu * 8);
            *(uint4*)&As[row][cu * 4] = v;
        }
    }
    {
        int k  = c.tid >> 2;
        int f0 = (c.tid & 3) * 16;
        const float* wp = W + (size_t)k * ldw + bn + f0;
        __half* bsh = (__half*)Bs;
        #pragma unroll
        for (int j = 0; j < 4; j++) {
            float4 v = *(const float4*)(wp + j * 4);
            int n0 = f0 + j * 4;
            bsh[(n0 + 0) * 72 + k] = __float2half(v.x);
            bsh[(n0 + 1) * 72 + k] = __float2half(v.y);
            bsh[(n0 + 2) * 72 + k] = __float2half(v.z);
            bsh[(n0 + 3) * 72 + k] = __float2half(v.w);
        }
    }
    __syncthreads();

    #pragma unroll
    for (int ks = 0; ks < 4; ks++) {
        int kc = ks * 8;
        uint32_t a[2][4], b[4][2];
        #pragma unroll
        for (int mt = 0; mt < 2; mt++) {
            int r0 = c.warp_m * 32 + mt * 16 + c.g;
            a[mt][0] = As[r0][kc + c.ti];
            a[mt][1] = As[r0 + 8][kc + c.ti];
            a[mt][2] = As[r0][kc + c.ti + 4];
            a[mt][3] = As[r0 + 8][kc + c.ti + 4];
        }
        #pragma unroll
        for (int nt = 0; nt < 4; nt++) {
            int n = c.warp_n * 32 + nt * 8 + c.g;
            b[nt][0] = Bs[n][kc + c.ti];
            b[nt][1] = Bs[n][kc + c.ti + 4];
        }
        #pragma unroll
        for (int mt = 0; mt < 2; mt++)
            #pragma unroll
            for (int nt = 0; nt < 4; nt++)
                mma16(acc[mt][nt], a[mt], b[nt]);
    }
}

// ---------------------------------------------------------------------------
// Tiled GEMM core (K up to 128)
// ---------------------------------------------------------------------------
__device__ __forceinline__ void gemm_core_h(
    const __half* __restrict__ A, const float* __restrict__ W,
    int M, int K, int lda, int ldw, int bm, int bn,
    uint32_t (&As)[128][12], uint32_t (&Bs)[64][12],
    const MmaCtx& c, float acc[2][4][4])
{
    const int arow = c.tid >> 1;
    const int ac8  = (c.tid & 1) * 8;
    const int wr   = c.tid >> 4;
    const int wc   = (c.tid & 15) * 4;
    __half* bsh = (__half*)Bs;

    for (int kt = 0; kt < K; kt += 16) {
        {
            int grow = bm + arow;
            uint4 v = make_uint4(0u, 0u, 0u, 0u);
            if (grow < M) v = *(const uint4*)(A + (size_t)grow * lda + kt + ac8);
            *(uint4*)&As[arow][ac8 >> 1] = v;
        }
        {
            float4 v = *(const float4*)(W + (size_t)(kt + wr) * ldw + bn + wc);
            bsh[(wc + 0) * 24 + wr] = __float2half(v.x);
            bsh[(wc + 1) * 24 + wr] = __float2half(v.y);
            bsh[(wc + 2) * 24 + wr] = __float2half(v.z);
            bsh[(wc + 3) * 24 + wr] = __float2half(v.w);
        }
        __syncthreads();

        uint32_t a[2][4], b[4][2];
        #pragma unroll
        for (int mt = 0; mt < 2; mt++) {
            int r0 = c.warp_m * 32 + mt * 16 + c.g;
            a[mt][0] = As[r0][c.ti];
            a[mt][1] = As[r0 + 8][c.ti];
            a[mt][2] = As[r0][c.ti + 4];
            a[mt][3] = As[r0 + 8][c.ti + 4];
        }
        #pragma unroll
        for (int nt = 0; nt < 4; nt++) {
            int n = c.warp_n * 32 + nt * 8 + c.g;
            b[nt][0] = Bs[n][c.ti];
            b[nt][1] = Bs[n][c.ti + 4];
        }
        #pragma unroll
        for (int mt = 0; mt < 2; mt++)
            #pragma unroll
            for (int nt = 0; nt < 4; nt++)
                mma16(acc[mt][nt], a[mt], b[nt]);
        __syncthreads();
    }
}

// ---------------------------------------------------------------------------
// Layer-1 P/Q GEMM (K=64 full-K core): P fp16 (+bias), Q e4m3 fp8
// ---------------------------------------------------------------------------
__global__ __launch_bounds__(256) void gemm_pq(
    const __half* __restrict__ A,
    const float* __restrict__ Wp, const float* __restrict__ Wq,
    const float* __restrict__ biasp,
    __half* __restrict__ Ph, uint8_t* __restrict__ Q8,
    int M, int N, int ldw)
{
    __shared__ uint32_t As[128][36];
    __shared__ uint32_t Bs[64][36];

    MmaCtx c = make_ctx();
    const int ntile = N >> 6;
    const int is_q  = (blockIdx.y >= (unsigned)ntile);
    const int bn    = (blockIdx.y - (is_q ? ntile : 0)) * 64;
    const int bm    = blockIdx.x * 128;
    const float* W  = is_q ? Wq : Wp;

    float acc[2][4][4] = {};
    gemm_fullk64(A, W, M, ldw, bm, bn, As, Bs, c, acc);

    #pragma unroll
    for (int mt = 0; mt < 2; mt++) {
        #pragma unroll
        for (int i = 0; i < 2; i++) {
            int row = bm + c.warp_m * 32 + mt * 16 + c.g + i * 8;
            if (row >= M) continue;
            #pragma unroll
            for (int nt = 0; nt < 4; nt++) {
                int col = bn + c.warp_n * 32 + nt * 8 + c.ti * 2;
                float v0 = acc[mt][nt][i * 2 + 0];
                float v1 = acc[mt][nt][i * 2 + 1];
                if (is_q) {
                    *(uint16_t*)(Q8 + (size_t)row * N + col) = f32x2_to_e4m3x2(v1, v0);
                } else {
                    v0 += biasp[col]; v1 += biasp[col + 1];
                    *(__half2*)(Ph + (size_t)row * N + col) = __floats2half2_rn(v0, v1);
                }
            }
        }
    }
}

// ---------------------------------------------------------------------------
// FUSED: H1 (smem-only) -> P2 (fp16, +bias) / Q2 (fp8)
// ---------------------------------------------------------------------------
__global__ __launch_bounds__(256) void gemm_h1pq2(
    const __half* __restrict__ S,
    const float* __restrict__ W1, const float* __restrict__ b1,
    const float* __restrict__ W2, const float* __restrict__ b2,
    const int* __restrict__ deg,
    __half* __restrict__ P2, uint8_t* __restrict__ Q28, int M)
{
    __shared__ uint32_t As[128][12];
    __shared__ uint32_t Bs[64][12];
    __shared__ uint32_t Ts[128][68];

    MmaCtx c = make_ctx();
    const int bm = blockIdx.x * 128;

    #pragma unroll
    for (int half = 0; half < 2; half++) {
        int bn = half * 64;
        float acc[2][4][4] = {};
        gemm_core_h(S, W1, M, 128, 128, 128, bm, bn, As, Bs, c, acc);
        #pragma unroll
        for (int mt = 0; mt < 2; mt++) {
            #pragma unroll
            for (int i = 0; i < 2; i++) {
                int row  = c.warp_m * 32 + mt * 16 + c.g + i * 8;
                int grow = bm + row;
                bool zero = (grow >= M) || (deg[grow < M ? grow : 0] == 0);
                #pragma unroll
                for (int nt = 0; nt < 4; nt++) {
                    int col = bn + c.warp_n * 32 + nt * 8 + c.ti * 2;
                    float v0 = acc[mt][nt][i * 2 + 0] + b1[col];
                    float v1 = acc[mt][nt][i * 2 + 1] + b1[col + 1];
                    v0 = fmaxf(v0, 0.f); v1 = fmaxf(v1, 0.f);
                    if (zero) { v0 = 0.f; v1 = 0.f; }
                    __half2 h = __floats2half2_rn(v0, v1);
                    Ts[row][col >> 1] = *(uint32_t*)&h;
                }
            }
        }
    }
    __syncthreads();

    const int wr = c.tid >> 4;
    const int wc = (c.tid & 15) * 4;
    __half* bsh = (__half*)Bs;

    #pragma unroll
    for (int half = 0; half < 2; half++) {
        const float* W = W2 + (size_t)half * 128 * 64;
        float acc[2][4][4] = {};
        for (int kt = 0; kt < 128; kt += 16) {
            {
                float4 v = *(const float4*)(W + (size_t)(kt + wr) * 64 + wc);
                bsh[(wc + 0) * 24 + wr] = __float2half(v.x);
                bsh[(wc + 1) * 24 + wr] = __float2half(v.y);
                bsh[(wc + 2) * 24 + wr] = __float2half(v.z);
                bsh[(wc + 3) * 24 + wr] = __float2half(v.w);
            }
            __syncthreads();
            uint32_t a[2][4], b[4][2];
            int kc = kt >> 1;
            #pragma unroll
            for (int mt = 0; mt < 2; mt++) {
                int r0 = c.warp_m * 32 + mt * 16 + c.g;
                a[mt][0] = Ts[r0][kc + c.ti];
                a[mt][1] = Ts[r0 + 8][kc + c.ti];
                a[mt][2] = Ts[r0][kc + c.ti + 4];
                a[mt][3] = Ts[r0 + 8][kc + c.ti + 4];
            }
            #pragma unroll
            for (int nt = 0; nt < 4; nt++) {
                int n = c.warp_n * 32 + nt * 8 + c.g;
                b[nt][0] = Bs[n][c.ti];
                b[nt][1] = Bs[n][c.ti + 4];
            }
            #pragma unroll
            for (int mt = 0; mt < 2; mt++)
                #pragma unroll
                for (int nt = 0; nt < 4; nt++)
                    mma16(acc[mt][nt], a[mt], b[nt]);
            __syncthreads();
        }
        #pragma unroll
        for (int mt = 0; mt < 2; mt++) {
            #pragma unroll
            for (int i = 0; i < 2; i++) {
                int row = bm + c.warp_m * 32 + mt * 16 + c.g + i * 8;
                if (row >= M) continue;
                #pragma unroll
                for (int nt = 0; nt < 4; nt++) {
                    int col = c.warp_n * 32 + nt * 8 + c.ti * 2;
                    float v0 = acc[mt][nt][i * 2 + 0];
                    float v1 = acc[mt][nt][i * 2 + 1];
                    if (!half) {
                        v0 += b2[col]; v1 += b2[col + 1];
                        *(__half2*)(P2 + (size_t)row * 64 + col) = __floats2half2_rn(v0, v1);
                    } else {
                        *(uint16_t*)(Q28 + (size_t)row * 64 + col) = f32x2_to_e4m3x2(v1, v0);
                    }
                }
            }
        }
    }
}

// ---------------------------------------------------------------------------
// H2 GEMM (K=64 full-K core) with pooled epilogue (smem batch aggregation)
// ---------------------------------------------------------------------------
#define POOL_SPAN 8

__global__ __launch_bounds__(256) void gemm_h2pool(
    const __half* __restrict__ A, const float* __restrict__ W,
    const float* __restrict__ bias, const int* __restrict__ deg,
    const int* __restrict__ nb, float* __restrict__ gsum, int M)
{
    __shared__ uint32_t As[128][36];
    __shared__ uint32_t Bs[64][36];
    __shared__ float pool[POOL_SPAN][GNN_DIM];

    MmaCtx c = make_ctx();
    const int bm = blockIdx.x * 128;

    int rlast = min(bm + 127, M - 1);
    int bmin = nb[bm < M ? bm : M - 1];
    int bmax = nb[rlast];
    bool use_smem = (bmax - bmin) < POOL_SPAN;

    for (int i = c.tid; i < POOL_SPAN * GNN_DIM; i += 256)
        ((float*)pool)[i] = 0.f;

    float acc[2][4][4] = {};
    gemm_fullk64(A, W, M, 64, bm, 0, As, Bs, c, acc);
    // gemm_fullk64 contains a __syncthreads(): pool zeroing is visible.

    #pragma unroll
    for (int mt = 0; mt < 2; mt++) {
        #pragma unroll
        for (int i = 0; i < 2; i++) {
            int row = bm + c.warp_m * 32 + mt * 16 + c.g + i * 8;
            if (row >= M) continue;
            bool zero = (deg[row] == 0);
            int batch = nb[row];
            #pragma unroll
            for (int nt = 0; nt < 4; nt++) {
                int col = c.warp_n * 32 + nt * 8 + c.ti * 2;
                float v0 = acc[mt][nt][i * 2 + 0] + bias[col];
                float v1 = acc[mt][nt][i * 2 + 1] + bias[col + 1];
                if (zero) { v0 = 0.f; v1 = 0.f; }
                if (use_smem) {
                    atomicAdd(&pool[batch - bmin][col],     v0);
                    atomicAdd(&pool[batch - bmin][col + 1], v1);
                } else {
                    atomicAdd(&gsum[batch * GNN_DIM + col],     v0);
                    atomicAdd(&gsum[batch * GNN_DIM + col + 1], v1);
                }
            }
        }
    }

    if (use_smem) {
        __syncthreads();
        for (int i = c.tid; i < POOL_SPAN * GNN_DIM; i += 256) {
            int g = i >> 6;
            if (bmin + g <= bmax) {
                float v = ((float*)pool)[i];
                atomicAdd(&gsum[(bmin + g) * GNN_DIM + (i & 63)], v);
            }
        }
    }
}

// ---------------------------------------------------------------------------
// Gather with fp8 Q: one warp per node, 32 fp8 feats per lane (2x uint4/edge).
// LPR = FEAT/32 lanes cover a row; EPI = 32/LPR edge slots in flight.
// __hfma2_relu fuses add+relu.
// ---------------------------------------------------------------------------
__device__ __forceinline__ __half2 h2add(__half2 a, __half2 b) { return __hadd2(a, b); }

template <int FEAT>   // 128 (layer1, LPR=4, EPI=8) or 64 (layer2, LPR=2, EPI=16)
__global__ __launch_bounds__(256) void gather32_fp8_kernel(
    const __half* __restrict__ P, const uint8_t* __restrict__ Q,
    const int* __restrict__ row_ptr, const int* __restrict__ deg,
    const int* __restrict__ csr, __half* __restrict__ S, int n_nodes)
{
    constexpr int LPR = FEAT / 32;
    constexpr int EPI = 32 / LPR;

    int node = (blockIdx.x * blockDim.x + threadIdx.x) >> 5;
    if (node >= n_nodes) return;
    int lane  = threadIdx.x & 31;
    int sub   = lane & (LPR - 1);
    int eslot = lane / LPR;

    // 32 fp16 features per lane: 4x uint4 of P
    const size_t foff = (size_t)node * FEAT + sub * 32;
    __half2 p[16];
    #pragma unroll
    for (int j = 0; j < 4; j++) {
        uint4 pv = *(const uint4*)(P + foff + j * 8);
        p[4*j+0] = *(__half2*)&pv.x; p[4*j+1] = *(__half2*)&pv.y;
        p[4*j+2] = *(__half2*)&pv.z; p[4*j+3] = *(__half2*)&pv.w;
    }

    const __half2 z2  = __float2half2_rn(0.f);
    const __half2 one = __float2half2_rn(1.f);
    __half2 a[16];
    #pragma unroll
    for (int j = 0; j < 16; j++) a[j] = z2;

    int d     = deg[node];
    int start = row_ptr[node];
    const size_t qoff = (size_t)sub * 32;   // byte offset within fp8 row

    for (int base = 0; base < d; base += 32) {
        int cnt = min(d - base, 32);
        int sidx = 0;
        if (lane < cnt) sidx = csr[start + base + lane];
        int iters = (cnt + EPI - 1) / EPI;

        int  i   = eslot;
        bool act = i < cnt;
        int  s   = __shfl_sync(0xffffffffu, sidx, i & 31);
        uint4 qv0 = make_uint4(0u,0u,0u,0u), qv1 = make_uint4(0u,0u,0u,0u);
        if (act) {
            const uint8_t* qp = Q + (size_t)s * FEAT + qoff;
            qv0 = *(const uint4*)qp;
            qv1 = *(const uint4*)(qp + 16);
        }

        for (int it = 1; it <= iters; it++) {
            int  i2   = it * EPI + eslot;
            bool act2 = i2 < cnt;
            int  s2   = __shfl_sync(0xffffffffu, sidx, i2 & 31);
            uint4 qn0 = make_uint4(0u,0u,0u,0u), qn1 = make_uint4(0u,0u,0u,0u);
            if (act2) {
                const uint8_t* qp = Q + (size_t)s2 * FEAT + qoff;
                qn0 = *(const uint4*)qp;
                qn1 = *(const uint4*)(qp + 16);
            }
            if (act) {
                const uint32_t* w0 = &qv0.x;
                const uint32_t* w1 = &qv1.x;
                #pragma unroll
                for (int j = 0; j < 4; j++) {
                    __half2 qlo = e4m3x2_to_h2((uint16_t)w0[j]);
                    __half2 qhi = e4m3x2_to_h2((uint16_t)(w0[j] >> 16));
                    a[2*j]   = h2add(a[2*j],   __hfma2_relu(qlo, one, p[2*j]));
                    a[2*j+1] = h2add(a[2*j+1], __hfma2_relu(qhi, one, p[2*j+1]));
                }
                #pragma unroll
                for (int j = 0; j < 4; j++) {
                    __half2 qlo = e4m3x2_to_h2((uint16_t)w1[j]);
                    __half2 qhi = e4m3x2_to_h2((uint16_t)(w1[j] >> 16));
                    a[8+2*j]   = h2add(a[8+2*j],   __hfma2_relu(qlo, one, p[8+2*j]));
                    a[8+2*j+1] = h2add(a[8+2*j+1], __hfma2_relu(qhi, one, p[8+2*j+1]));
                }
            }
            qv0 = qn0; qv1 = qn1; act = act2;
        }
    }

    // reduce accumulators across edge slots
    #pragma unroll
    for (int off = LPR; off < 32; off <<= 1) {
        #pragma unroll
        for (int j = 0; j < 16; j++) {
            uint32_t u = __shfl_xor_sync(0xffffffffu, *(uint32_t*)&a[j], off);
            a[j] = h2add(a[j], *(__half2*)&u);
        }
    }

    if (eslot == 0) {
        float inv = 1.0f / (float)(d > 0 ? d : 1);
        #pragma unroll
        for (int blk = 0; blk < 4; blk++) {
            uint4 o;
            uint32_t* ow = &o.x;
            #pragma unroll
            for (int j = 0; j < 4; j++) {
                float2 f = __half22float2(a[blk * 4 + j]);
                __half2 h = __floats2half2_rn(f.x * inv, f.y * inv);
                ow[j] = *(uint32_t*)&h;
            }
            *(uint4*)(S + foff + blk * 8) = o;
        }
    }
}

// ---------------------------------------------------------------------------
// Actor head
// ---------------------------------------------------------------------------
__global__ __launch_bounds__(256) void head_kernel(
    const float* __restrict__ state,
    const float* __restrict__ gsum, const int* __restrict__ gcnt,
    const float* __restrict__ fc1_w, const float* __restrict__ fc1_b,
    const float* __restrict__ fc2_w, const float* __restrict__ fc2_b,
    const float* __restrict__ mean_w, const float* __restrict__ mean_b,
    const float* __restrict__ ls_w, const float* __restrict__ ls_b,
    float* __restrict__ out, int n_graphs)
{
    __shared__ float z[128];
    __shared__ float h1[256];
    __shared__ float h2[256];
    int b = blockIdx.x;
    int t = threadIdx.x;
    if (b >= n_graphs) return;

    if (t < 64) {
        z[t] = state[b * 64 + t];
    } else if (t < 128) {
        float c = fmaxf((float)gcnt[b], 1.f);
        z[t] = gsum[b * GNN_DIM + (t - 64)] / c;
    }
    __syncthreads();

    {
        float s = fc1_b[t];
        #pragma unroll 4
        for (int k = 0; k < 128; k++) s += z[k] * fc1_w[k * 256 + t];
        h1[t] = fmaxf(s, 0.f);
    }
    __syncthreads();
    {
        float s = fc2_b[t];
        #pragma unroll 4
        for (int k = 0; k < 256; k++) s += h1[k] * fc2_w[k * 256 + t];
        h2[t] = fmaxf(s, 0.f);
    }
    __syncthreads();

    if (t < ACTION_DIM) {
        float s = mean_b[t];
        #pragma unroll 4
        for (int k = 0; k < 256; k++) s += h2[k] * mean_w[k * ACTION_DIM + t];
        out[b * ACTION_DIM + t] = s;
    } else if (t < 2 * ACTION_DIM) {
        int j = t - ACTION_DIM;
        float s = ls_b[j];
        #pragma unroll 4
        for (int k = 0; k < 256; k++) s += h2[k] * ls_w[k * ACTION_DIM + j];
        s = fminf(fmaxf(s, -20.f), 2.f);
        out[n_graphs * ACTION_DIM + b * ACTION_DIM + j] = s;
    }
}

// ---------------------------------------------------------------------------
// Launch (R10 structure: CSR side fork only, single main chain)
// ---------------------------------------------------------------------------
extern "C" void kernel_launch(void* const* d_in, const int* in_sizes, int n_in,
                              void* d_out, int out_size)
{
    const float* state  = (const float*)d_in[0];
    const float* x      = (const float*)d_in[1];
    const int*   eidx   = (const int*)  d_in[2];
    const int*   nbatch = (const int*)  d_in[3];
    const float* g1w1   = (const float*)d_in[4];
    const float* g1b1   = (const float*)d_in[5];
    const float* g1w2   = (const float*)d_in[6];
    const float* g1b2   = (const float*)d_in[7];
    const float* g2w1   = (const float*)d_in[8];
    const float* g2b1   = (const float*)d_in[9];
    const float* g2w2   = (const float*)d_in[10];
    const float* g2b2   = (const float*)d_in[11];
    const float* fc1_w  = (const float*)d_in[12];
    const float* fc1_b  = (const float*)d_in[13];
    const float* fc2_w  = (const float*)d_in[14];
    const float* fc2_b  = (const float*)d_in[15];
    const float* mean_w = (const float*)d_in[16];
    const float* mean_b = (const float*)d_in[17];
    const float* ls_w   = (const float*)d_in[18];
    const float* ls_b   = (const float*)d_in[19];
    float* out = (float*)d_out;

    const int n_graphs = in_sizes[0] / 64;
    const int n_nodes  = in_sizes[1] / NODE_DIM;
    const int n_edges  = in_sizes[2] / 2;
    const int* e_src = eidx;
    const int* e_dst = eidx + n_edges;

    __half *bufXh, *bufPh, *bufSh;
    uint8_t *bufQ8;
    float *gsum;
    int *deg, *cursor, *rowptr, *csr, *gcnt, *agg, *flag;
    cudaGetSymbolAddress((void**)&bufXh,  g_bufXh);
    cudaGetSymbolAddress((void**)&bufPh,  g_bufPh);
    cudaGetSymbolAddress((void**)&bufQ8,  g_bufQ8);
    cudaGetSymbolAddress((void**)&bufSh,  g_bufSh);
    cudaGetSymbolAddress((void**)&deg,    g_deg);
    cudaGetSymbolAddress((void**)&cursor, g_cursor);
    cudaGetSymbolAddress((void**)&rowptr, g_rowptr);
    cudaGetSymbolAddress((void**)&csr,    g_csr);
    cudaGetSymbolAddress((void**)&agg,    g_agg);
    cudaGetSymbolAddress((void**)&flag,   g_flag);
    cudaGetSymbolAddress((void**)&gsum,   g_gsum);
    cudaGetSymbolAddress((void**)&gcnt,   g_gcnt);

    static cudaStream_t s_side = nullptr;
    static cudaEvent_t  s_ev0 = nullptr, s_ev1 = nullptr;
    if (!s_side) {
        cudaStreamCreateWithFlags(&s_side, cudaStreamNonBlocking);
        cudaEventCreateWithFlags(&s_ev0, cudaEventDisableTiming);
        cudaEventCreateWithFlags(&s_ev1, cudaEventDisableTiming);
    }

    const int ncvt = n_nodes * NODE_DIM / 4;
    const int mb = (n_nodes + 127) / 128;
    const int eblocks  = (n_edges + 255) / 256;
    const int e4blocks = (n_edges / 4 + 256) / 256;
    const int sblocks  = (n_nodes + SCAN_BLK - 1) / SCAN_BLK;
    const int gblocks  = (n_nodes * 32 + 255) / 256;   // one warp per node

    // ---- zero first (both chains depend on it), then fork ----
    zero_side_kernel<<<(n_nodes + 255) / 256, 256>>>(deg, gcnt, flag, n_nodes, n_graphs);
    cudaEventRecord(s_ev0, 0);
    cudaStreamWaitEvent(s_side, s_ev0, 0);

    // ---- side stream: CSR chain ----
    hist_count4_kernel<<<e4blocks, 256, 0, s_side>>>(e_dst, deg, nbatch, gcnt, n_edges, n_nodes);
    scan_lb_kernel<<<sblocks, SCAN_BLK, 0, s_side>>>(deg, rowptr, cursor, agg, flag, n_nodes);
    fill_kernel<<<eblocks, 256, 0, s_side>>>(e_src, e_dst, cursor, csr, n_edges);
    cudaEventRecord(s_ev1, s_side);

    // ---- main stream: x cvt + L1 P/Q GEMM (independent of CSR) ----
    init_main_kernel<<<(ncvt + 255) / 256, 256>>>(x, bufXh, gsum, n_graphs, ncvt);
    gemm_pq<<<dim3(mb, 4), 256>>>(bufXh, g1w1, g1w1 + 64 * 128, g1b1,
                                  bufPh, bufQ8, n_nodes, 128, 128);

    // ---- join ----
    cudaStreamWaitEvent(0, s_ev1, 0);

    gather32_fp8_kernel<128><<<gblocks, 256>>>(bufPh, bufQ8, rowptr, deg, csr, bufSh, n_nodes);
    gemm_h1pq2<<<mb, 256>>>(bufSh, g1w2, g1b2, g2w1, g2b1, deg,
                            bufPh, bufQ8, n_nodes);
    gather32_fp8_kernel<64><<<gblocks, 256>>>(bufPh, bufQ8, rowptr, deg, csr, bufSh, n_nodes);
    gemm_h2pool<<<mb, 256>>>(bufSh, g2w2, g2b2, deg, nbatch, gsum, n_nodes);
    head_kernel<<<n_graphs, 256>>>(state, gsum, gcnt,
                                   fc1_w, fc1_b, fc2_w, fc2_b,
                                   mean_w, mean_b, ls_w, ls_b,
                                   out, n_graphs);
}

// round 13
// speedup vs baseline: 1.0980x; 1.0980x over previous
#include <cuda_runtime.h>
#include <cuda_fp16.h>
#include <cstdint>

// ---------------------------------------------------------------------------
// Problem constants
// ---------------------------------------------------------------------------
#define MAX_NODES 50000
#define MAX_EDGES 800000
#define NODE_DIM  64
#define GNN_H     128
#define GNN_DIM   64
#define NB        128
#define HIDDEN    256
#define ACTION_DIM 8
#define SCAN_BLK  1024
#define SBLOCKS_MAX ((MAX_NODES + SCAN_BLK - 1) / SCAN_BLK)

// ---------------------------------------------------------------------------
// Device scratch
// ---------------------------------------------------------------------------
__device__ __half  g_bufXh[MAX_NODES * NODE_DIM];
__device__ __half  g_bufPh[MAX_NODES * GNN_H];
__device__ uint8_t g_bufQ8[MAX_NODES * GNN_H];   // e4m3 Q tables
__device__ __half  g_bufSh[MAX_NODES * GNN_H];
__device__ int     g_deg[MAX_NODES];
__device__ int     g_cursor[MAX_NODES];
__device__ int     g_rowptr[MAX_NODES];
__device__ int     g_csr[MAX_EDGES];
__device__ int     g_agg[SBLOCKS_MAX];
__device__ int     g_flag[SBLOCKS_MAX];
__device__ float   g_gsum[NB * GNN_DIM];
__device__ int     g_gcnt[NB];

// ---------------------------------------------------------------------------
// fp8 conversion helpers (e4m3)
// ---------------------------------------------------------------------------
__device__ __forceinline__ __half2 e4m3x2_to_h2(uint16_t v)
{
    uint32_t r;
    asm("cvt.rn.f16x2.e4m3x2 %0, %1;" : "=r"(r) : "h"(v));
    return *(__half2*)&r;
}

// packs: high byte = hi, low byte = lo
__device__ __forceinline__ uint16_t f32x2_to_e4m3x2(float hi, float lo)
{
    uint16_t r;
    asm("cvt.rn.satfinite.e4m3x2.f32 %0, %1, %2;" : "=h"(r) : "f"(hi), "f"(lo));
    return r;
}

// ---------------------------------------------------------------------------
// zero (main stream, pre-fork)
// ---------------------------------------------------------------------------
__global__ void zero_side_kernel(int* __restrict__ deg, int* __restrict__ gcnt,
                                 int* __restrict__ flag, int n_nodes, int n_graphs)
{
    int i = blockIdx.x * blockDim.x + threadIdx.x;
    if (i < n_nodes) deg[i] = 0;
    if (i < n_graphs) gcnt[i] = 0;
    if (i < SBLOCKS_MAX) flag[i] = 0;
}

__global__ void hist_count4_kernel(const int* __restrict__ dst, int* __restrict__ deg,
                                   const int* __restrict__ nb, int* __restrict__ gcnt,
                                   int n_edges, int n_nodes)
{
    int t = blockIdx.x * blockDim.x + threadIdx.x;
    int base = t * 4;
    if (base + 3 < n_edges) {
        int4 d = *(const int4*)(dst + base);
        atomicAdd(&deg[d.x], 1);
        atomicAdd(&deg[d.y], 1);
        atomicAdd(&deg[d.z], 1);
        atomicAdd(&deg[d.w], 1);
    } else {
        for (int i = base; i < n_edges; i++) atomicAdd(&deg[dst[i]], 1);
    }
    if (base + 3 < n_nodes) {
        int4 b = *(const int4*)(nb + base);
        atomicAdd(&gcnt[b.x], 1);
        atomicAdd(&gcnt[b.y], 1);
        atomicAdd(&gcnt[b.z], 1);
        atomicAdd(&gcnt[b.w], 1);
    } else if (base < n_nodes) {
        for (int i = base; i < n_nodes; i++) atomicAdd(&gcnt[nb[i]], 1);
    }
}

// Single-kernel scan: block-local Hillis-Steele + warp-parallel lookback.
__global__ __launch_bounds__(SCAN_BLK) void scan_lb_kernel(
    const int* __restrict__ deg, int* __restrict__ rowptr, int* __restrict__ cursor,
    int* __restrict__ agg, int* __restrict__ flag, int n)
{
    __shared__ int sm[SCAN_BLK];
    __shared__ int s_run;
    int t = threadIdx.x, b = blockIdx.x;
    int i = b * SCAN_BLK + t;
    int v = (i < n) ? deg[i] : 0;
    sm[t] = v;
    __syncthreads();
    #pragma unroll
    for (int off = 1; off < SCAN_BLK; off <<= 1) {
        int u = (t >= off) ? sm[t - off] : 0;
        __syncthreads();
        sm[t] += u;
        __syncthreads();
    }
    if (t == 0) {
        agg[b] = sm[SCAN_BLK - 1];
        __threadfence();
        atomicExch(&flag[b], 1);
    }
    if (t < 32) {
        int run = 0;
        for (int j = t; j < b; j += 32) {
            while (atomicAdd(&flag[j], 0) == 0) { }
            __threadfence();
            run += *(volatile const int*)&agg[j];
        }
        #pragma unroll
        for (int off = 16; off; off >>= 1)
            run += __shfl_down_sync(0xffffffffu, run, off);
        if (t == 0) s_run = run;
    }
    __syncthreads();
    if (i < n) {
        int r = s_run + sm[t] - v;   // exclusive
        rowptr[i] = r;
        cursor[i] = r;
    }
}

__global__ void fill_kernel(const int* __restrict__ src, const int* __restrict__ dst,
                            int* __restrict__ cursor, int* __restrict__ csr, int n_edges)
{
    int e = blockIdx.x * blockDim.x + threadIdx.x;
    if (e >= n_edges) return;
    int pos = atomicAdd(&cursor[dst[e]], 1);
    csr[pos] = src[e];
}

// ---------------------------------------------------------------------------
// Main-stream init: convert x to fp16 + zero gsum
// ---------------------------------------------------------------------------
__global__ void init_main_kernel(const float* __restrict__ x, __half* __restrict__ xh,
                                 float* __restrict__ gsum, int n_graphs, int ncvt)
{
    int i = blockIdx.x * blockDim.x + threadIdx.x;
    if (i < ncvt) {
        float4 v = ((const float4*)x)[i];
        uint2 o;
        *(__half2*)&o.x = __floats2half2_rn(v.x, v.y);
        *(__half2*)&o.y = __floats2half2_rn(v.z, v.w);
        ((uint2*)xh)[i] = o;
    }
    if (i < n_graphs * GNN_DIM) gsum[i] = 0.f;
}

// ---------------------------------------------------------------------------
// MMA machinery
// ---------------------------------------------------------------------------
struct MmaCtx { int tid, g, ti, warp_m, warp_n; };

__device__ __forceinline__ MmaCtx make_ctx()
{
    MmaCtx c;
    c.tid = threadIdx.x;
    int lane = c.tid & 31;
    int wid  = c.tid >> 5;
    c.g = lane >> 2;
    c.ti = lane & 3;
    c.warp_m = wid & 3;
    c.warp_n = wid >> 2;
    return c;
}

__device__ __forceinline__ void mma16(float c[4], const uint32_t a[4], const uint32_t b[2])
{
    asm volatile(
        "mma.sync.aligned.m16n8k16.row.col.f32.f16.f16.f32 "
        "{%0,%1,%2,%3}, {%4,%5,%6,%7}, {%8,%9}, {%0,%1,%2,%3};"
        : "+f"(c[0]), "+f"(c[1]), "+f"(c[2]), "+f"(c[3])
        : "r"(a[0]), "r"(a[1]), "r"(a[2]), "r"(a[3]), "r"(b[0]), "r"(b[1]));
}

// ---------------------------------------------------------------------------
// Full-K single-sync GEMM core for K=64 (lda = 64 halves)
// ---------------------------------------------------------------------------
__device__ __forceinline__ void gemm_fullk64(
    const __half* __restrict__ A, const float* __restrict__ W,
    int M, int ldw, int bm, int bn,
    uint32_t (&As)[128][36], uint32_t (&Bs)[64][36],
    const MmaCtx& c, float acc[2][4][4])
{
    {
        int row   = c.tid >> 1;
        int cbase = (c.tid & 1) * 4;
        bool ok = (bm + row) < M;
        const __half* ap = A + (size_t)(bm + row) * 64;
        #pragma unroll
        for (int cc = 0; cc < 4; cc++) {
            int cu = cbase + cc;
            uint4 v = make_uint4(0u, 0u, 0u, 0u);
            if (ok) v = *(const uint4*)(ap + cu * 8);
            *(uint4*)&As[row][cu * 4] = v;
        }
    }
    {
        int k  = c.tid >> 2;
        int f0 = (c.tid & 3) * 16;
        const float* wp = W + (size_t)k * ldw + bn + f0;
        __half* bsh = (__half*)Bs;
        #pragma unroll
        for (int j = 0; j < 4; j++) {
            float4 v = *(const float4*)(wp + j * 4);
            int n0 = f0 + j * 4;
            bsh[(n0 + 0) * 72 + k] = __float2half(v.x);
            bsh[(n0 + 1) * 72 + k] = __float2half(v.y);
            bsh[(n0 + 2) * 72 + k] = __float2half(v.z);
            bsh[(n0 + 3) * 72 + k] = __float2half(v.w);
        }
    }
    __syncthreads();

    #pragma unroll
    for (int ks = 0; ks < 4; ks++) {
        int kc = ks * 8;
        uint32_t a[2][4], b[4][2];
        #pragma unroll
        for (int mt = 0; mt < 2; mt++) {
            int r0 = c.warp_m * 32 + mt * 16 + c.g;
            a[mt][0] = As[r0][kc + c.ti];
            a[mt][1] = As[r0 + 8][kc + c.ti];
            a[mt][2] = As[r0][kc + c.ti + 4];
            a[mt][3] = As[r0 + 8][kc + c.ti + 4];
        }
        #pragma unroll
        for (int nt = 0; nt < 4; nt++) {
            int n = c.warp_n * 32 + nt * 8 + c.g;
            b[nt][0] = Bs[n][kc + c.ti];
            b[nt][1] = Bs[n][kc + c.ti + 4];
        }
        #pragma unroll
        for (int mt = 0; mt < 2; mt++)
            #pragma unroll
            for (int nt = 0; nt < 4; nt++)
                mma16(acc[mt][nt], a[mt], b[nt]);
    }
}

// ---------------------------------------------------------------------------
// Tiled GEMM core (K up to 128)
// ---------------------------------------------------------------------------
__device__ __forceinline__ void gemm_core_h(
    const __half* __restrict__ A, const float* __restrict__ W,
    int M, int K, int lda, int ldw, int bm, int bn,
    uint32_t (&As)[128][12], uint32_t (&Bs)[64][12],
    const MmaCtx& c, float acc[2][4][4])
{
    const int arow = c.tid >> 1;
    const int ac8  = (c.tid & 1) * 8;
    const int wr   = c.tid >> 4;
    const int wc   = (c.tid & 15) * 4;
    __half* bsh = (__half*)Bs;

    for (int kt = 0; kt < K; kt += 16) {
        {
            int grow = bm + arow;
            uint4 v = make_uint4(0u, 0u, 0u, 0u);
            if (grow < M) v = *(const uint4*)(A + (size_t)grow * lda + kt + ac8);
            *(uint4*)&As[arow][ac8 >> 1] = v;
        }
        {
            float4 v = *(const float4*)(W + (size_t)(kt + wr) * ldw + bn + wc);
            bsh[(wc + 0) * 24 + wr] = __float2half(v.x);
            bsh[(wc + 1) * 24 + wr] = __float2half(v.y);
            bsh[(wc + 2) * 24 + wr] = __float2half(v.z);
            bsh[(wc + 3) * 24 + wr] = __float2half(v.w);
        }
        __syncthreads();

        uint32_t a[2][4], b[4][2];
        #pragma unroll
        for (int mt = 0; mt < 2; mt++) {
            int r0 = c.warp_m * 32 + mt * 16 + c.g;
            a[mt][0] = As[r0][c.ti];
            a[mt][1] = As[r0 + 8][c.ti];
            a[mt][2] = As[r0][c.ti + 4];
            a[mt][3] = As[r0 + 8][c.ti + 4];
        }
        #pragma unroll
        for (int nt = 0; nt < 4; nt++) {
            int n = c.warp_n * 32 + nt * 8 + c.g;
            b[nt][0] = Bs[n][c.ti];
            b[nt][1] = Bs[n][c.ti + 4];
        }
        #pragma unroll
        for (int mt = 0; mt < 2; mt++)
            #pragma unroll
            for (int nt = 0; nt < 4; nt++)
                mma16(acc[mt][nt], a[mt], b[nt]);
        __syncthreads();
    }
}

// ---------------------------------------------------------------------------
// Layer-1 P/Q GEMM (K=64 full-K core): P fp16 (+bias), Q e4m3 fp8
// ---------------------------------------------------------------------------
__global__ __launch_bounds__(256) void gemm_pq(
    const __half* __restrict__ A,
    const float* __restrict__ Wp, const float* __restrict__ Wq,
    const float* __restrict__ biasp,
    __half* __restrict__ Ph, uint8_t* __restrict__ Q8,
    int M, int N, int ldw)
{
    __shared__ uint32_t As[128][36];
    __shared__ uint32_t Bs[64][36];

    MmaCtx c = make_ctx();
    const int ntile = N >> 6;
    const int is_q  = (blockIdx.y >= (unsigned)ntile);
    const int bn    = (blockIdx.y - (is_q ? ntile : 0)) * 64;
    const int bm    = blockIdx.x * 128;
    const float* W  = is_q ? Wq : Wp;

    float acc[2][4][4] = {};
    gemm_fullk64(A, W, M, ldw, bm, bn, As, Bs, c, acc);

    #pragma unroll
    for (int mt = 0; mt < 2; mt++) {
        #pragma unroll
        for (int i = 0; i < 2; i++) {
            int row = bm + c.warp_m * 32 + mt * 16 + c.g + i * 8;
            if (row >= M) continue;
            #pragma unroll
            for (int nt = 0; nt < 4; nt++) {
                int col = bn + c.warp_n * 32 + nt * 8 + c.ti * 2;
                float v0 = acc[mt][nt][i * 2 + 0];
                float v1 = acc[mt][nt][i * 2 + 1];
                if (is_q) {
                    *(uint16_t*)(Q8 + (size_t)row * N + col) = f32x2_to_e4m3x2(v1, v0);
                } else {
                    v0 += biasp[col]; v1 += biasp[col + 1];
                    *(__half2*)(Ph + (size_t)row * N + col) = __floats2half2_rn(v0, v1);
                }
            }
        }
    }
}

// ---------------------------------------------------------------------------
// FUSED: H1 (smem-only) -> P2 (fp16, +bias) / Q2 (fp8)
// ---------------------------------------------------------------------------
__global__ __launch_bounds__(256) void gemm_h1pq2(
    const __half* __restrict__ S,
    const float* __restrict__ W1, const float* __restrict__ b1,
    const float* __restrict__ W2, const float* __restrict__ b2,
    const int* __restrict__ deg,
    __half* __restrict__ P2, uint8_t* __restrict__ Q28, int M)
{
    __shared__ uint32_t As[128][12];
    __shared__ uint32_t Bs[64][12];
    __shared__ uint32_t Ts[128][68];

    MmaCtx c = make_ctx();
    const int bm = blockIdx.x * 128;

    #pragma unroll
    for (int half = 0; half < 2; half++) {
        int bn = half * 64;
        float acc[2][4][4] = {};
        gemm_core_h(S, W1, M, 128, 128, 128, bm, bn, As, Bs, c, acc);
        #pragma unroll
        for (int mt = 0; mt < 2; mt++) {
            #pragma unroll
            for (int i = 0; i < 2; i++) {
                int row  = c.warp_m * 32 + mt * 16 + c.g + i * 8;
                int grow = bm + row;
                bool zero = (grow >= M) || (deg[grow < M ? grow : 0] == 0);
                #pragma unroll
                for (int nt = 0; nt < 4; nt++) {
                    int col = bn + c.warp_n * 32 + nt * 8 + c.ti * 2;
                    float v0 = acc[mt][nt][i * 2 + 0] + b1[col];
                    float v1 = acc[mt][nt][i * 2 + 1] + b1[col + 1];
                    v0 = fmaxf(v0, 0.f); v1 = fmaxf(v1, 0.f);
                    if (zero) { v0 = 0.f; v1 = 0.f; }
                    __half2 h = __floats2half2_rn(v0, v1);
                    Ts[row][col >> 1] = *(uint32_t*)&h;
                }
            }
        }
    }
    __syncthreads();

    const int wr = c.tid >> 4;
    const int wc = (c.tid & 15) * 4;
    __half* bsh = (__half*)Bs;

    #pragma unroll
    for (int half = 0; half < 2; half++) {
        const float* W = W2 + (size_t)half * 128 * 64;
        float acc[2][4][4] = {};
        for (int kt = 0; kt < 128; kt += 16) {
            {
                float4 v = *(const float4*)(W + (size_t)(kt + wr) * 64 + wc);
                bsh[(wc + 0) * 24 + wr] = __float2half(v.x);
                bsh[(wc + 1) * 24 + wr] = __float2half(v.y);
                bsh[(wc + 2) * 24 + wr] = __float2half(v.z);
                bsh[(wc + 3) * 24 + wr] = __float2half(v.w);
            }
            __syncthreads();
            uint32_t a[2][4], b[4][2];
            int kc = kt >> 1;
            #pragma unroll
            for (int mt = 0; mt < 2; mt++) {
                int r0 = c.warp_m * 32 + mt * 16 + c.g;
                a[mt][0] = Ts[r0][kc + c.ti];
                a[mt][1] = Ts[r0 + 8][kc + c.ti];
                a[mt][2] = Ts[r0][kc + c.ti + 4];
                a[mt][3] = Ts[r0 + 8][kc + c.ti + 4];
            }
            #pragma unroll
            for (int nt = 0; nt < 4; nt++) {
                int n = c.warp_n * 32 + nt * 8 + c.g;
                b[nt][0] = Bs[n][c.ti];
                b[nt][1] = Bs[n][c.ti + 4];
            }
            #pragma unroll
            for (int mt = 0; mt < 2; mt++)
                #pragma unroll
                for (int nt = 0; nt < 4; nt++)
                    mma16(acc[mt][nt], a[mt], b[nt]);
            __syncthreads();
        }
        #pragma unroll
        for (int mt = 0; mt < 2; mt++) {
            #pragma unroll
            for (int i = 0; i < 2; i++) {
                int row = bm + c.warp_m * 32 + mt * 16 + c.g + i * 8;
                if (row >= M) continue;
                #pragma unroll
                for (int nt = 0; nt < 4; nt++) {
                    int col = c.warp_n * 32 + nt * 8 + c.ti * 2;
                    float v0 = acc[mt][nt][i * 2 + 0];
                    float v1 = acc[mt][nt][i * 2 + 1];
                    if (!half) {
                        v0 += b2[col]; v1 += b2[col + 1];
                        *(__half2*)(P2 + (size_t)row * 64 + col) = __floats2half2_rn(v0, v1);
                    } else {
                        *(uint16_t*)(Q28 + (size_t)row * 64 + col) = f32x2_to_e4m3x2(v1, v0);
                    }
                }
            }
        }
    }
}

// ---------------------------------------------------------------------------
// H2 GEMM (K=64 full-K core) with pooled epilogue (smem batch aggregation)
// ---------------------------------------------------------------------------
#define POOL_SPAN 8

__global__ __launch_bounds__(256) void gemm_h2pool(
    const __half* __restrict__ A, const float* __restrict__ W,
    const float* __restrict__ bias, const int* __restrict__ deg,
    const int* __restrict__ nb, float* __restrict__ gsum, int M)
{
    __shared__ uint32_t As[128][36];
    __shared__ uint32_t Bs[64][36];
    __shared__ float pool[POOL_SPAN][GNN_DIM];

    MmaCtx c = make_ctx();
    const int bm = blockIdx.x * 128;

    int rlast = min(bm + 127, M - 1);
    int bmin = nb[bm < M ? bm : M - 1];
    int bmax = nb[rlast];
    bool use_smem = (bmax - bmin) < POOL_SPAN;

    for (int i = c.tid; i < POOL_SPAN * GNN_DIM; i += 256)
        ((float*)pool)[i] = 0.f;

    float acc[2][4][4] = {};
    gemm_fullk64(A, W, M, 64, bm, 0, As, Bs, c, acc);
    // gemm_fullk64 contains a __syncthreads(): pool zeroing is visible.

    #pragma unroll
    for (int mt = 0; mt < 2; mt++) {
        #pragma unroll
        for (int i = 0; i < 2; i++) {
            int row = bm + c.warp_m * 32 + mt * 16 + c.g + i * 8;
            if (row >= M) continue;
            bool zero = (deg[row] == 0);
            int batch = nb[row];
            #pragma unroll
            for (int nt = 0; nt < 4; nt++) {
                int col = c.warp_n * 32 + nt * 8 + c.ti * 2;
                float v0 = acc[mt][nt][i * 2 + 0] + bias[col];
                float v1 = acc[mt][nt][i * 2 + 1] + bias[col + 1];
                if (zero) { v0 = 0.f; v1 = 0.f; }
                if (use_smem) {
                    atomicAdd(&pool[batch - bmin][col],     v0);
                    atomicAdd(&pool[batch - bmin][col + 1], v1);
                } else {
                    atomicAdd(&gsum[batch * GNN_DIM + col],     v0);
                    atomicAdd(&gsum[batch * GNN_DIM + col + 1], v1);
                }
            }
        }
    }

    if (use_smem) {
        __syncthreads();
        for (int i = c.tid; i < POOL_SPAN * GNN_DIM; i += 256) {
            int g = i >> 6;
            if (bmin + g <= bmax) {
                float v = ((float*)pool)[i];
                atomicAdd(&gsum[(bmin + g) * GNN_DIM + (i & 63)], v);
            }
        }
    }
}

// ---------------------------------------------------------------------------
// Gather with fp8 Q: one warp per node, 16 fp8 feats per lane (uint4 loads).
// LPR lanes cover a row (FEAT = LPR*16); EPI = 32/LPR edges in flight.
// __hfma2_relu fuses add+relu (only delta vs the R10 best).
// ---------------------------------------------------------------------------
__device__ __forceinline__ __half2 h2add(__half2 a, __half2 b) { return __hadd2(a, b); }

template <int LPR>   // 8 -> FEAT=128 (layer1), 4 -> FEAT=64 (layer2)
__global__ __launch_bounds__(256) void gather16_fp8_kernel(
    const __half* __restrict__ P, const uint8_t* __restrict__ Q,
    const int* __restrict__ row_ptr, const int* __restrict__ deg,
    const int* __restrict__ csr, __half* __restrict__ S, int n_nodes)
{
    constexpr int FEAT = LPR * 16;
    constexpr int EPI  = 32 / LPR;

    int node = (blockIdx.x * blockDim.x + threadIdx.x) >> 5;
    if (node >= n_nodes) return;
    int lane  = threadIdx.x & 31;
    int sub   = lane & (LPR - 1);
    int eslot = lane / LPR;

    const size_t foff = (size_t)node * FEAT + sub * 16;
    uint4 pv0 = *(const uint4*)(P + foff);
    uint4 pv1 = *(const uint4*)(P + foff + 8);
    __half2 p[8];
    p[0] = *(__half2*)&pv0.x; p[1] = *(__half2*)&pv0.y;
    p[2] = *(__half2*)&pv0.z; p[3] = *(__half2*)&pv0.w;
    p[4] = *(__half2*)&pv1.x; p[5] = *(__half2*)&pv1.y;
    p[6] = *(__half2*)&pv1.z; p[7] = *(__half2*)&pv1.w;

    const __half2 z2  = __float2half2_rn(0.f);
    const __half2 one = __float2half2_rn(1.f);
    __half2 a[8];
    #pragma unroll
    for (int j = 0; j < 8; j++) a[j] = z2;

    int d     = deg[node];
    int start = row_ptr[node];
    const size_t qoff = (size_t)sub * 16;   // byte offset within row

    for (int base = 0; base < d; base += 32) {
        int cnt = min(d - base, 32);
        int sidx = 0;
        if (lane < cnt) sidx = csr[start + base + lane];
        int iters = (cnt + EPI - 1) / EPI;

        int  i   = eslot;
        bool act = i < cnt;
        int  s   = __shfl_sync(0xffffffffu, sidx, i & 31);
        uint4 qv = make_uint4(0u, 0u, 0u, 0u);
        if (act) qv = *(const uint4*)(Q + (size_t)s * FEAT + qoff);

        for (int it = 1; it <= iters; it++) {
            int  i2   = it * EPI + eslot;
            bool act2 = i2 < cnt;
            int  s2   = __shfl_sync(0xffffffffu, sidx, i2 & 31);
            uint4 qn  = make_uint4(0u, 0u, 0u, 0u);
            if (act2) qn = *(const uint4*)(Q + (size_t)s2 * FEAT + qoff);
            if (act) {
                const uint32_t* w = &qv.x;
                #pragma unroll
                for (int j = 0; j < 4; j++) {
                    __half2 qlo = e4m3x2_to_h2((uint16_t)w[j]);
                    __half2 qhi = e4m3x2_to_h2((uint16_t)(w[j] >> 16));
                    a[2*j]   = h2add(a[2*j],   __hfma2_relu(qlo, one, p[2*j]));
                    a[2*j+1] = h2add(a[2*j+1], __hfma2_relu(qhi, one, p[2*j+1]));
                }
            }
            qv = qn; act = act2;
        }
    }

    // reduce accumulators across edge slots
    #pragma unroll
    for (int off = LPR; off < 32; off <<= 1) {
        #pragma unroll
        for (int j = 0; j < 8; j++) {
            uint32_t u = __shfl_xor_sync(0xffffffffu, *(uint32_t*)&a[j], off);
            a[j] = h2add(a[j], *(__half2*)&u);
        }
    }

    if (eslot == 0) {
        float inv = 1.0f / (float)(d > 0 ? d : 1);
        uint4 o0, o1;
        uint32_t* ow = &o0.x;
        #pragma unroll
        for (int j = 0; j < 8; j++) {
            float2 f = __half22float2(a[j]);
            __half2 h = __floats2half2_rn(f.x * inv, f.y * inv);
            if (j < 4) ow[j] = *(uint32_t*)&h;
            else       (&o1.x)[j - 4] = *(uint32_t*)&h;
        }
        *(uint4*)(S + foff)     = o0;
        *(uint4*)(S + foff + 8) = o1;
    }
}

// ---------------------------------------------------------------------------
// Actor head
// ---------------------------------------------------------------------------
__global__ __launch_bounds__(256) void head_kernel(
    const float* __restrict__ state,
    const float* __restrict__ gsum, const int* __restrict__ gcnt,
    const float* __restrict__ fc1_w, const float* __restrict__ fc1_b,
    const float* __restrict__ fc2_w, const float* __restrict__ fc2_b,
    const float* __restrict__ mean_w, const float* __restrict__ mean_b,
    const float* __restrict__ ls_w, const float* __restrict__ ls_b,
    float* __restrict__ out, int n_graphs)
{
    __shared__ float z[128];
    __shared__ float h1[256];
    __shared__ float h2[256];
    int b = blockIdx.x;
    int t = threadIdx.x;
    if (b >= n_graphs) return;

    if (t < 64) {
        z[t] = state[b * 64 + t];
    } else if (t < 128) {
        float c = fmaxf((float)gcnt[b], 1.f);
        z[t] = gsum[b * GNN_DIM + (t - 64)] / c;
    }
    __syncthreads();

    {
        float s = fc1_b[t];
        #pragma unroll 4
        for (int k = 0; k < 128; k++) s += z[k] * fc1_w[k * 256 + t];
        h1[t] = fmaxf(s, 0.f);
    }
    __syncthreads();
    {
        float s = fc2_b[t];
        #pragma unroll 4
        for (int k = 0; k < 256; k++) s += h1[k] * fc2_w[k * 256 + t];
        h2[t] = fmaxf(s, 0.f);
    }
    __syncthreads();

    if (t < ACTION_DIM) {
        float s = mean_b[t];
        #pragma unroll 4
        for (int k = 0; k < 256; k++) s += h2[k] * mean_w[k * ACTION_DIM + t];
        out[b * ACTION_DIM + t] = s;
    } else if (t < 2 * ACTION_DIM) {
        int j = t - ACTION_DIM;
        float s = ls_b[j];
        #pragma unroll 4
        for (int k = 0; k < 256; k++) s += h2[k] * ls_w[k * ACTION_DIM + j];
        s = fminf(fmaxf(s, -20.f), 2.f);
        out[n_graphs * ACTION_DIM + b * ACTION_DIM + j] = s;
    }
}

// ---------------------------------------------------------------------------
// Launch (R10 structure: CSR side fork only, single main chain)
// ---------------------------------------------------------------------------
extern "C" void kernel_launch(void* const* d_in, const int* in_sizes, int n_in,
                              void* d_out, int out_size)
{
    const float* state  = (const float*)d_in[0];
    const float* x      = (const float*)d_in[1];
    const int*   eidx   = (const int*)  d_in[2];
    const int*   nbatch = (const int*)  d_in[3];
    const float* g1w1   = (const float*)d_in[4];
    const float* g1b1   = (const float*)d_in[5];
    const float* g1w2   = (const float*)d_in[6];
    const float* g1b2   = (const float*)d_in[7];
    const float* g2w1   = (const float*)d_in[8];
    const float* g2b1   = (const float*)d_in[9];
    const float* g2w2   = (const float*)d_in[10];
    const float* g2b2   = (const float*)d_in[11];
    const float* fc1_w  = (const float*)d_in[12];
    const float* fc1_b  = (const float*)d_in[13];
    const float* fc2_w  = (const float*)d_in[14];
    const float* fc2_b  = (const float*)d_in[15];
    const float* mean_w = (const float*)d_in[16];
    const float* mean_b = (const float*)d_in[17];
    const float* ls_w   = (const float*)d_in[18];
    const float* ls_b   = (const float*)d_in[19];
    float* out = (float*)d_out;

    const int n_graphs = in_sizes[0] / 64;
    const int n_nodes  = in_sizes[1] / NODE_DIM;
    const int n_edges  = in_sizes[2] / 2;
    const int* e_src = eidx;
    const int* e_dst = eidx + n_edges;

    __half *bufXh, *bufPh, *bufSh;
    uint8_t *bufQ8;
    float *gsum;
    int *deg, *cursor, *rowptr, *csr, *gcnt, *agg, *flag;
    cudaGetSymbolAddress((void**)&bufXh,  g_bufXh);
    cudaGetSymbolAddress((void**)&bufPh,  g_bufPh);
    cudaGetSymbolAddress((void**)&bufQ8,  g_bufQ8);
    cudaGetSymbolAddress((void**)&bufSh,  g_bufSh);
    cudaGetSymbolAddress((void**)&deg,    g_deg);
    cudaGetSymbolAddress((void**)&cursor, g_cursor);
    cudaGetSymbolAddress((void**)&rowptr, g_rowptr);
    cudaGetSymbolAddress((void**)&csr,    g_csr);
    cudaGetSymbolAddress((void**)&agg,    g_agg);
    cudaGetSymbolAddress((void**)&flag,   g_flag);
    cudaGetSymbolAddress((void**)&gsum,   g_gsum);
    cudaGetSymbolAddress((void**)&gcnt,   g_gcnt);

    static cudaStream_t s_side = nullptr;
    static cudaEvent_t  s_ev0 = nullptr, s_ev1 = nullptr;
    if (!s_side) {
        cudaStreamCreateWithFlags(&s_side, cudaStreamNonBlocking);
        cudaEventCreateWithFlags(&s_ev0, cudaEventDisableTiming);
        cudaEventCreateWithFlags(&s_ev1, cudaEventDisableTiming);
    }

    const int ncvt = n_nodes * NODE_DIM / 4;
    const int mb = (n_nodes + 127) / 128;
    const int eblocks  = (n_edges + 255) / 256;
    const int e4blocks = (n_edges / 4 + 256) / 256;
    const int sblocks  = (n_nodes + SCAN_BLK - 1) / SCAN_BLK;
    const int gblocks  = (n_nodes * 32 + 255) / 256;   // one warp per node

    // ---- zero first (both chains depend on it), then fork ----
    zero_side_kernel<<<(n_nodes + 255) / 256, 256>>>(deg, gcnt, flag, n_nodes, n_graphs);
    cudaEventRecord(s_ev0, 0);
    cudaStreamWaitEvent(s_side, s_ev0, 0);

    // ---- side stream: CSR chain ----
    hist_count4_kernel<<<e4blocks, 256, 0, s_side>>>(e_dst, deg, nbatch, gcnt, n_edges, n_nodes);
    scan_lb_kernel<<<sblocks, SCAN_BLK, 0, s_side>>>(deg, rowptr, cursor, agg, flag, n_nodes);
    fill_kernel<<<eblocks, 256, 0, s_side>>>(e_src, e_dst, cursor, csr, n_edges);
    cudaEventRecord(s_ev1, s_side);

    // ---- main stream: x cvt + L1 P/Q GEMM (independent of CSR) ----
    init_main_kernel<<<(ncvt + 255) / 256, 256>>>(x, bufXh, gsum, n_graphs, ncvt);
    gemm_pq<<<dim3(mb, 4), 256>>>(bufXh, g1w1, g1w1 + 64 * 128, g1b1,
                                  bufPh, bufQ8, n_nodes, 128, 128);

    // ---- join ----
    cudaStreamWaitEvent(0, s_ev1, 0);

    gather16_fp8_kernel<8><<<gblocks, 256>>>(bufPh, bufQ8, rowptr, deg, csr, bufSh, n_nodes);
    gemm_h1pq2<<<mb, 256>>>(bufSh, g1w2, g1b2, g2w1, g2b1, deg,
                            bufPh, bufQ8, n_nodes);
    gather16_fp8_kernel<4><<<gblocks, 256>>>(bufPh, bufQ8, rowptr, deg, csr, bufSh, n_nodes);
    gemm_h2pool<<<mb, 256>>>(bufSh, g2w2, g2b2, deg, nbatch, gsum, n_nodes);
    head_kernel<<<n_graphs, 256>>>(state, gsum, gcnt,
                                   fc1_w, fc1_b, fc2_w, fc2_b,
                                   mean_w, mean_b, ls_w, ls_b,
                                   out, n_graphs);
}

// round 14
// speedup vs baseline: 1.1388x; 1.0372x over previous
#include <cuda_runtime.h>
#include <cuda_fp16.h>
#include <cstdint>

// ---------------------------------------------------------------------------
// Problem constants
// ---------------------------------------------------------------------------
#define MAX_NODES 50000
#define MAX_EDGES 800000
#define NODE_DIM  64
#define GNN_H     128
#define GNN_DIM   64
#define NB        128
#define HIDDEN    256
#define ACTION_DIM 8
#define SCAN_BLK  1024
#define SBLOCKS_MAX ((MAX_NODES + SCAN_BLK - 1) / SCAN_BLK)

// ---------------------------------------------------------------------------
// Device scratch
// ---------------------------------------------------------------------------
__device__ __half  g_bufXh[MAX_NODES * NODE_DIM];
__device__ __half  g_bufPh[MAX_NODES * GNN_H];
__device__ uint8_t g_bufQ8[MAX_NODES * GNN_H];   // e4m3 Q tables
__device__ __half  g_bufSh[MAX_NODES * GNN_H];
__device__ int     g_deg[MAX_NODES];
__device__ int     g_cursor[MAX_NODES];
__device__ int     g_rowptr[MAX_NODES];
__device__ int     g_csr[MAX_EDGES];
__device__ int     g_agg[SBLOCKS_MAX];
__device__ int     g_flag[SBLOCKS_MAX];
__device__ float   g_gsum[NB * GNN_DIM];
__device__ int     g_gcnt[NB];

// ---------------------------------------------------------------------------
// fp8 conversion helpers (e4m3)
// ---------------------------------------------------------------------------
__device__ __forceinline__ __half2 e4m3x2_to_h2(uint16_t v)
{
    uint32_t r;
    asm("cvt.rn.f16x2.e4m3x2 %0, %1;" : "=r"(r) : "h"(v));
    return *(__half2*)&r;
}

// packs: high byte = hi, low byte = lo
__device__ __forceinline__ uint16_t f32x2_to_e4m3x2(float hi, float lo)
{
    uint16_t r;
    asm("cvt.rn.satfinite.e4m3x2.f32 %0, %1, %2;" : "=h"(r) : "f"(hi), "f"(lo));
    return r;
}

// ---------------------------------------------------------------------------
// zero (main stream, pre-fork)
// ---------------------------------------------------------------------------
__global__ void zero_side_kernel(int* __restrict__ deg, int* __restrict__ gcnt,
                                 int* __restrict__ flag, int n_nodes, int n_graphs)
{
    int i = blockIdx.x * blockDim.x + threadIdx.x;
    if (i < n_nodes) deg[i] = 0;
    if (i < n_graphs) gcnt[i] = 0;
    if (i < SBLOCKS_MAX) flag[i] = 0;
}

__global__ void hist_count4_kernel(const int* __restrict__ dst, int* __restrict__ deg,
                                   const int* __restrict__ nb, int* __restrict__ gcnt,
                                   int n_edges, int n_nodes)
{
    int t = blockIdx.x * blockDim.x + threadIdx.x;
    int base = t * 4;
    if (base + 3 < n_edges) {
        int4 d = *(const int4*)(dst + base);
        atomicAdd(&deg[d.x], 1);
        atomicAdd(&deg[d.y], 1);
        atomicAdd(&deg[d.z], 1);
        atomicAdd(&deg[d.w], 1);
    } else {
        for (int i = base; i < n_edges; i++) atomicAdd(&deg[dst[i]], 1);
    }
    if (base + 3 < n_nodes) {
        int4 b = *(const int4*)(nb + base);
        atomicAdd(&gcnt[b.x], 1);
        atomicAdd(&gcnt[b.y], 1);
        atomicAdd(&gcnt[b.z], 1);
        atomicAdd(&gcnt[b.w], 1);
    } else if (base < n_nodes) {
        for (int i = base; i < n_nodes; i++) atomicAdd(&gcnt[nb[i]], 1);
    }
}

// Single-kernel scan: block-local Hillis-Steele + warp-parallel lookback.
__global__ __launch_bounds__(SCAN_BLK) void scan_lb_kernel(
    const int* __restrict__ deg, int* __restrict__ rowptr, int* __restrict__ cursor,
    int* __restrict__ agg, int* __restrict__ flag, int n)
{
    __shared__ int sm[SCAN_BLK];
    __shared__ int s_run;
    int t = threadIdx.x, b = blockIdx.x;
    int i = b * SCAN_BLK + t;
    int v = (i < n) ? deg[i] : 0;
    sm[t] = v;
    __syncthreads();
    #pragma unroll
    for (int off = 1; off < SCAN_BLK; off <<= 1) {
        int u = (t >= off) ? sm[t - off] : 0;
        __syncthreads();
        sm[t] += u;
        __syncthreads();
    }
    if (t == 0) {
        agg[b] = sm[SCAN_BLK - 1];
        __threadfence();
        atomicExch(&flag[b], 1);
    }
    if (t < 32) {
        int run = 0;
        for (int j = t; j < b; j += 32) {
            while (atomicAdd(&flag[j], 0) == 0) { }
            __threadfence();
            run += *(volatile const int*)&agg[j];
        }
        #pragma unroll
        for (int off = 16; off; off >>= 1)
            run += __shfl_down_sync(0xffffffffu, run, off);
        if (t == 0) s_run = run;
    }
    __syncthreads();
    if (i < n) {
        int r = s_run + sm[t] - v;   // exclusive
        rowptr[i] = r;
        cursor[i] = r;
    }
}

__global__ void fill_kernel(const int* __restrict__ src, const int* __restrict__ dst,
                            int* __restrict__ cursor, int* __restrict__ csr, int n_edges)
{
    int e = blockIdx.x * blockDim.x + threadIdx.x;
    if (e >= n_edges) return;
    int pos = atomicAdd(&cursor[dst[e]], 1);
    csr[pos] = src[e];
}

// ---------------------------------------------------------------------------
// Main-stream init: convert x to fp16 + zero gsum
// ---------------------------------------------------------------------------
__global__ void init_main_kernel(const float* __restrict__ x, __half* __restrict__ xh,
                                 float* __restrict__ gsum, int n_graphs, int ncvt)
{
    int i = blockIdx.x * blockDim.x + threadIdx.x;
    if (i < ncvt) {
        float4 v = ((const float4*)x)[i];
        uint2 o;
        *(__half2*)&o.x = __floats2half2_rn(v.x, v.y);
        *(__half2*)&o.y = __floats2half2_rn(v.z, v.w);
        ((uint2*)xh)[i] = o;
    }
    if (i < n_graphs * GNN_DIM) gsum[i] = 0.f;
}

// ---------------------------------------------------------------------------
// MMA machinery
// ---------------------------------------------------------------------------
struct MmaCtx { int tid, g, ti, warp_m, warp_n; };

__device__ __forceinline__ MmaCtx make_ctx()
{
    MmaCtx c;
    c.tid = threadIdx.x;
    int lane = c.tid & 31;
    int wid  = c.tid >> 5;
    c.g = lane >> 2;
    c.ti = lane & 3;
    c.warp_m = wid & 3;
    c.warp_n = wid >> 2;
    return c;
}

__device__ __forceinline__ void mma16(float c[4], const uint32_t a[4], const uint32_t b[2])
{
    asm volatile(
        "mma.sync.aligned.m16n8k16.row.col.f32.f16.f16.f32 "
        "{%0,%1,%2,%3}, {%4,%5,%6,%7}, {%8,%9}, {%0,%1,%2,%3};"
        : "+f"(c[0]), "+f"(c[1]), "+f"(c[2]), "+f"(c[3])
        : "r"(a[0]), "r"(a[1]), "r"(a[2]), "r"(a[3]), "r"(b[0]), "r"(b[1]));
}

// ---------------------------------------------------------------------------
// Full-K single-sync GEMM core for K=64 (lda = 64 halves) - used by h2pool
// ---------------------------------------------------------------------------
__device__ __forceinline__ void gemm_fullk64(
    const __half* __restrict__ A, const float* __restrict__ W,
    int M, int ldw, int bm, int bn,
    uint32_t (&As)[128][36], uint32_t (&Bs)[64][36],
    const MmaCtx& c, float acc[2][4][4])
{
    {
        int row   = c.tid >> 1;
        int cbase = (c.tid & 1) * 4;
        bool ok = (bm + row) < M;
        const __half* ap = A + (size_t)(bm + row) * 64;
        #pragma unroll
        for (int cc = 0; cc < 4; cc++) {
            int cu = cbase + cc;
            uint4 v = make_uint4(0u, 0u, 0u, 0u);
            if (ok) v = *(const uint4*)(ap + cu * 8);
            *(uint4*)&As[row][cu * 4] = v;
        }
    }
    {
        int k  = c.tid >> 2;
        int f0 = (c.tid & 3) * 16;
        const float* wp = W + (size_t)k * ldw + bn + f0;
        __half* bsh = (__half*)Bs;
        #pragma unroll
        for (int j = 0; j < 4; j++) {
            float4 v = *(const float4*)(wp + j * 4);
            int n0 = f0 + j * 4;
            bsh[(n0 + 0) * 72 + k] = __float2half(v.x);
            bsh[(n0 + 1) * 72 + k] = __float2half(v.y);
            bsh[(n0 + 2) * 72 + k] = __float2half(v.z);
            bsh[(n0 + 3) * 72 + k] = __float2half(v.w);
        }
    }
    __syncthreads();

    #pragma unroll
    for (int ks = 0; ks < 4; ks++) {
        int kc = ks * 8;
        uint32_t a[2][4], b[4][2];
        #pragma unroll
        for (int mt = 0; mt < 2; mt++) {
            int r0 = c.warp_m * 32 + mt * 16 + c.g;
            a[mt][0] = As[r0][kc + c.ti];
            a[mt][1] = As[r0 + 8][kc + c.ti];
            a[mt][2] = As[r0][kc + c.ti + 4];
            a[mt][3] = As[r0 + 8][kc + c.ti + 4];
        }
        #pragma unroll
        for (int nt = 0; nt < 4; nt++) {
            int n = c.warp_n * 32 + nt * 8 + c.g;
            b[nt][0] = Bs[n][kc + c.ti];
            b[nt][1] = Bs[n][kc + c.ti + 4];
        }
        #pragma unroll
        for (int mt = 0; mt < 2; mt++)
            #pragma unroll
            for (int nt = 0; nt < 4; nt++)
                mma16(acc[mt][nt], a[mt], b[nt]);
    }
}

// ---------------------------------------------------------------------------
// Tiled GEMM core (K up to 128) with register double-buffering of the
// next tile's A/W global loads (issued before the sync, hidden by compute).
// ---------------------------------------------------------------------------
__device__ __forceinline__ void gemm_core_h(
    const __half* __restrict__ A, const float* __restrict__ W,
    int M, int K, int lda, int ldw, int bm, int bn,
    uint32_t (&As)[128][12], uint32_t (&Bs)[64][12],
    const MmaCtx& c, float acc[2][4][4])
{
    const int arow = c.tid >> 1;
    const int ac8  = (c.tid & 1) * 8;
    const int wr   = c.tid >> 4;
    const int wc   = (c.tid & 15) * 4;
    __half* bsh = (__half*)Bs;

    const int grow = bm + arow;
    const bool aok = grow < M;
    const __half* ap = A + (size_t)grow * lda;

    uint4 areg = make_uint4(0u, 0u, 0u, 0u);
    if (aok) areg = *(const uint4*)(ap + ac8);
    float4 wreg = *(const float4*)(W + (size_t)wr * ldw + bn + wc);

    for (int kt = 0; kt < K; kt += 16) {
        *(uint4*)&As[arow][ac8 >> 1] = areg;
        bsh[(wc + 0) * 24 + wr] = __float2half(wreg.x);
        bsh[(wc + 1) * 24 + wr] = __float2half(wreg.y);
        bsh[(wc + 2) * 24 + wr] = __float2half(wreg.z);
        bsh[(wc + 3) * 24 + wr] = __float2half(wreg.w);
        if (kt + 16 < K) {
            if (aok) areg = *(const uint4*)(ap + kt + 16 + ac8);
            wreg = *(const float4*)(W + (size_t)(kt + 16 + wr) * ldw + bn + wc);
        }
        __syncthreads();

        uint32_t a[2][4], b[4][2];
        #pragma unroll
        for (int mt = 0; mt < 2; mt++) {
            int r0 = c.warp_m * 32 + mt * 16 + c.g;
            a[mt][0] = As[r0][c.ti];
            a[mt][1] = As[r0 + 8][c.ti];
            a[mt][2] = As[r0][c.ti + 4];
            a[mt][3] = As[r0 + 8][c.ti + 4];
        }
        #pragma unroll
        for (int nt = 0; nt < 4; nt++) {
            int n = c.warp_n * 32 + nt * 8 + c.g;
            b[nt][0] = Bs[n][c.ti];
            b[nt][1] = Bs[n][c.ti + 4];
        }
        #pragma unroll
        for (int mt = 0; mt < 2; mt++)
            #pragma unroll
            for (int nt = 0; nt < 4; nt++)
                mma16(acc[mt][nt], a[mt], b[nt]);
        __syncthreads();
    }
}

// ---------------------------------------------------------------------------
// Layer-1 P/Q GEMM: one block computes BOTH 64-col n-tiles of its half
// (A staged once; W registers prefetched across tiles).
// blockIdx.y: 0 = P half (bias), 1 = Q half (fp8 out).
// ---------------------------------------------------------------------------
__global__ __launch_bounds__(256) void gemm_pq(
    const __half* __restrict__ A,
    const float* __restrict__ Wp, const float* __restrict__ Wq,
    const float* __restrict__ biasp,
    __half* __restrict__ Ph, uint8_t* __restrict__ Q8,
    int M, int N, int ldw)
{
    __shared__ uint32_t As[128][36];
    __shared__ uint32_t Bs[64][36];

    MmaCtx c = make_ctx();
    const int is_q = blockIdx.y;
    const int bm   = blockIdx.x * 128;
    const float* W = is_q ? Wq : Wp;

    // stage A (full K=64) once
    {
        int row   = c.tid >> 1;
        int cbase = (c.tid & 1) * 4;
        bool ok = (bm + row) < M;
        const __half* ap = A + (size_t)(bm + row) * 64;
        #pragma unroll
        for (int cc = 0; cc < 4; cc++) {
            int cu = cbase + cc;
            uint4 v = make_uint4(0u, 0u, 0u, 0u);
            if (ok) v = *(const uint4*)(ap + cu * 8);
            *(uint4*)&As[row][cu * 4] = v;
        }
    }

    const int k  = c.tid >> 2;
    const int f0 = (c.tid & 3) * 16;
    __half* bsh = (__half*)Bs;
    float4 wreg[4];
    #pragma unroll
    for (int j = 0; j < 4; j++)
        wreg[j] = *(const float4*)(W + (size_t)k * ldw + f0 + j * 4);

    for (int t = 0; t < 2; t++) {
        const int bn = t * 64;
        #pragma unroll
        for (int j = 0; j < 4; j++) {
            int n0 = f0 + j * 4;
            bsh[(n0 + 0) * 72 + k] = __float2half(wreg[j].x);
            bsh[(n0 + 1) * 72 + k] = __float2half(wreg[j].y);
            bsh[(n0 + 2) * 72 + k] = __float2half(wreg[j].z);
            bsh[(n0 + 3) * 72 + k] = __float2half(wreg[j].w);
        }
        if (t == 0) {
            #pragma unroll
            for (int j = 0; j < 4; j++)
                wreg[j] = *(const float4*)(W + (size_t)k * ldw + 64 + f0 + j * 4);
        }
        __syncthreads();

        float acc[2][4][4] = {};
        #pragma unroll
        for (int ks = 0; ks < 4; ks++) {
            int kc = ks * 8;
            uint32_t a[2][4], b[4][2];
            #pragma unroll
            for (int mt = 0; mt < 2; mt++) {
                int r0 = c.warp_m * 32 + mt * 16 + c.g;
                a[mt][0] = As[r0][kc + c.ti];
                a[mt][1] = As[r0 + 8][kc + c.ti];
                a[mt][2] = As[r0][kc + c.ti + 4];
                a[mt][3] = As[r0 + 8][kc + c.ti + 4];
            }
            #pragma unroll
            for (int nt = 0; nt < 4; nt++) {
                int n = c.warp_n * 32 + nt * 8 + c.g;
                b[nt][0] = Bs[n][kc + c.ti];
                b[nt][1] = Bs[n][kc + c.ti + 4];
            }
            #pragma unroll
            for (int mt = 0; mt < 2; mt++)
                #pragma unroll
                for (int nt = 0; nt < 4; nt++)
                    mma16(acc[mt][nt], a[mt], b[nt]);
        }

        // epilogue for this n-tile
        #pragma unroll
        for (int mt = 0; mt < 2; mt++) {
            #pragma unroll
            for (int i = 0; i < 2; i++) {
                int row = bm + c.warp_m * 32 + mt * 16 + c.g + i * 8;
                if (row >= M) continue;
                #pragma unroll
                for (int nt = 0; nt < 4; nt++) {
                    int col = bn + c.warp_n * 32 + nt * 8 + c.ti * 2;
                    float v0 = acc[mt][nt][i * 2 + 0];
                    float v1 = acc[mt][nt][i * 2 + 1];
                    if (is_q) {
                        *(uint16_t*)(Q8 + (size_t)row * N + col) = f32x2_to_e4m3x2(v1, v0);
                    } else {
                        v0 += biasp[col]; v1 += biasp[col + 1];
                        *(__half2*)(Ph + (size_t)row * N + col) = __floats2half2_rn(v0, v1);
                    }
                }
            }
        }
        __syncthreads();
    }
}

// ---------------------------------------------------------------------------
// FUSED: H1 (smem-only) -> P2 (fp16, +bias) / Q2 (fp8)
// Stage2 W loads register-prefetched.
// ---------------------------------------------------------------------------
__global__ __launch_bounds__(256) void gemm_h1pq2(
    const __half* __restrict__ S,
    const float* __restrict__ W1, const float* __restrict__ b1,
    const float* __restrict__ W2, const float* __restrict__ b2,
    const int* __restrict__ deg,
    __half* __restrict__ P2, uint8_t* __restrict__ Q28, int M)
{
    __shared__ uint32_t As[128][12];
    __shared__ uint32_t Bs[64][12];
    __shared__ uint32_t Ts[128][68];

    MmaCtx c = make_ctx();
    const int bm = blockIdx.x * 128;

    #pragma unroll
    for (int half = 0; half < 2; half++) {
        int bn = half * 64;
        float acc[2][4][4] = {};
        gemm_core_h(S, W1, M, 128, 128, 128, bm, bn, As, Bs, c, acc);
        #pragma unroll
        for (int mt = 0; mt < 2; mt++) {
            #pragma unroll
            for (int i = 0; i < 2; i++) {
                int row  = c.warp_m * 32 + mt * 16 + c.g + i * 8;
                int grow = bm + row;
                bool zero = (grow >= M) || (deg[grow < M ? grow : 0] == 0);
                #pragma unroll
                for (int nt = 0; nt < 4; nt++) {
                    int col = bn + c.warp_n * 32 + nt * 8 + c.ti * 2;
                    float v0 = acc[mt][nt][i * 2 + 0] + b1[col];
                    float v1 = acc[mt][nt][i * 2 + 1] + b1[col + 1];
                    v0 = fmaxf(v0, 0.f); v1 = fmaxf(v1, 0.f);
                    if (zero) { v0 = 0.f; v1 = 0.f; }
                    __half2 h = __floats2half2_rn(v0, v1);
                    Ts[row][col >> 1] = *(uint32_t*)&h;
                }
            }
        }
    }
    __syncthreads();

    const int wr = c.tid >> 4;
    const int wc = (c.tid & 15) * 4;
    __half* bsh = (__half*)Bs;

    #pragma unroll
    for (int half = 0; half < 2; half++) {
        const float* W = W2 + (size_t)half * 128 * 64;
        float acc[2][4][4] = {};
        float4 wv = *(const float4*)(W + (size_t)wr * 64 + wc);
        for (int kt = 0; kt < 128; kt += 16) {
            bsh[(wc + 0) * 24 + wr] = __float2half(wv.x);
            bsh[(wc + 1) * 24 + wr] = __float2half(wv.y);
            bsh[(wc + 2) * 24 + wr] = __float2half(wv.z);
            bsh[(wc + 3) * 24 + wr] = __float2half(wv.w);
            if (kt + 16 < 128)
                wv = *(const float4*)(W + (size_t)(kt + 16 + wr) * 64 + wc);
            __syncthreads();
            uint32_t a[2][4], b[4][2];
            int kc = kt >> 1;
            #pragma unroll
            for (int mt = 0; mt < 2; mt++) {
                int r0 = c.warp_m * 32 + mt * 16 + c.g;
                a[mt][0] = Ts[r0][kc + c.ti];
                a[mt][1] = Ts[r0 + 8][kc + c.ti];
                a[mt][2] = Ts[r0][kc + c.ti + 4];
                a[mt][3] = Ts[r0 + 8][kc + c.ti + 4];
            }
            #pragma unroll
            for (int nt = 0; nt < 4; nt++) {
                int n = c.warp_n * 32 + nt * 8 + c.g;
                b[nt][0] = Bs[n][c.ti];
                b[nt][1] = Bs[n][c.ti + 4];
            }
            #pragma unroll
            for (int mt = 0; mt < 2; mt++)
                #pragma unroll
                for (int nt = 0; nt < 4; nt++)
                    mma16(acc[mt][nt], a[mt], b[nt]);
            __syncthreads();
        }
        #pragma unroll
        for (int mt = 0; mt < 2; mt++) {
            #pragma unroll
            for (int i = 0; i < 2; i++) {
                int row = bm + c.warp_m * 32 + mt * 16 + c.g + i * 8;
                if (row >= M) continue;
                #pragma unroll
                for (int nt = 0; nt < 4; nt++) {
                    int col = c.warp_n * 32 + nt * 8 + c.ti * 2;
                    float v0 = acc[mt][nt][i * 2 + 0];
                    float v1 = acc[mt][nt][i * 2 + 1];
                    if (!half) {
                        v0 += b2[col]; v1 += b2[col + 1];
                        *(__half2*)(P2 + (size_t)row * 64 + col) = __floats2half2_rn(v0, v1);
                    } else {
                        *(uint16_t*)(Q28 + (size_t)row * 64 + col) = f32x2_to_e4m3x2(v1, v0);
                    }
                }
            }
        }
    }
}

// ---------------------------------------------------------------------------
// H2 GEMM (K=64 full-K core) with pooled epilogue (smem batch aggregation)
// ---------------------------------------------------------------------------
#define POOL_SPAN 8

__global__ __launch_bounds__(256) void gemm_h2pool(
    const __half* __restrict__ A, const float* __restrict__ W,
    const float* __restrict__ bias, const int* __restrict__ deg,
    const int* __restrict__ nb, float* __restrict__ gsum, int M)
{
    __shared__ uint32_t As[128][36];
    __shared__ uint32_t Bs[64][36];
    __shared__ float pool[POOL_SPAN][GNN_DIM];

    MmaCtx c = make_ctx();
    const int bm = blockIdx.x * 128;

    int rlast = min(bm + 127, M - 1);
    int bmin = nb[bm < M ? bm : M - 1];
    int bmax = nb[rlast];
    bool use_smem = (bmax - bmin) < POOL_SPAN;

    for (int i = c.tid; i < POOL_SPAN * GNN_DIM; i += 256)
        ((float*)pool)[i] = 0.f;

    float acc[2][4][4] = {};
    gemm_fullk64(A, W, M, 64, bm, 0, As, Bs, c, acc);
    // gemm_fullk64 contains a __syncthreads(): pool zeroing is visible.

    #pragma unroll
    for (int mt = 0; mt < 2; mt++) {
        #pragma unroll
        for (int i = 0; i < 2; i++) {
            int row = bm + c.warp_m * 32 + mt * 16 + c.g + i * 8;
            if (row >= M) continue;
            bool zero = (deg[row] == 0);
            int batch = nb[row];
            #pragma unroll
            for (int nt = 0; nt < 4; nt++) {
                int col = c.warp_n * 32 + nt * 8 + c.ti * 2;
                float v0 = acc[mt][nt][i * 2 + 0] + bias[col];
                float v1 = acc[mt][nt][i * 2 + 1] + bias[col + 1];
                if (zero) { v0 = 0.f; v1 = 0.f; }
                if (use_smem) {
                    atomicAdd(&pool[batch - bmin][col],     v0);
                    atomicAdd(&pool[batch - bmin][col + 1], v1);
                } else {
                    atomicAdd(&gsum[batch * GNN_DIM + col],     v0);
                    atomicAdd(&gsum[batch * GNN_DIM + col + 1], v1);
                }
            }
        }
    }

    if (use_smem) {
        __syncthreads();
        for (int i = c.tid; i < POOL_SPAN * GNN_DIM; i += 256) {
            int g = i >> 6;
            if (bmin + g <= bmax) {
                float v = ((float*)pool)[i];
                atomicAdd(&gsum[(bmin + g) * GNN_DIM + (i & 63)], v);
            }
        }
    }
}

// ---------------------------------------------------------------------------
// Gather with fp8 Q: one warp per node, 16 fp8 feats per lane (uint4 loads).
// LPR lanes cover a row (FEAT = LPR*16); EPI = 32/LPR edges in flight.
// __hfma2_relu fuses add+relu. (FROZEN: structure is at its local optimum.)
// ---------------------------------------------------------------------------
__device__ __forceinline__ __half2 h2add(__half2 a, __half2 b) { return __hadd2(a, b); }

template <int LPR>   // 8 -> FEAT=128 (layer1), 4 -> FEAT=64 (layer2)
__global__ __launch_bounds__(256) void gather16_fp8_kernel(
    const __half* __restrict__ P, const uint8_t* __restrict__ Q,
    const int* __restrict__ row_ptr, const int* __restrict__ deg,
    const int* __restrict__ csr, __half* __restrict__ S, int n_nodes)
{
    constexpr int FEAT = LPR * 16;
    constexpr int EPI  = 32 / LPR;

    int node = (blockIdx.x * blockDim.x + threadIdx.x) >> 5;
    if (node >= n_nodes) return;
    int lane  = threadIdx.x & 31;
    int sub   = lane & (LPR - 1);
    int eslot = lane / LPR;

    const size_t foff = (size_t)node * FEAT + sub * 16;
    uint4 pv0 = *(const uint4*)(P + foff);
    uint4 pv1 = *(const uint4*)(P + foff + 8);
    __half2 p[8];
    p[0] = *(__half2*)&pv0.x; p[1] = *(__half2*)&pv0.y;
    p[2] = *(__half2*)&pv0.z; p[3] = *(__half2*)&pv0.w;
    p[4] = *(__half2*)&pv1.x; p[5] = *(__half2*)&pv1.y;
    p[6] = *(__half2*)&pv1.z; p[7] = *(__half2*)&pv1.w;

    const __half2 z2  = __float2half2_rn(0.f);
    const __half2 one = __float2half2_rn(1.f);
    __half2 a[8];
    #pragma unroll
    for (int j = 0; j < 8; j++) a[j] = z2;

    int d     = deg[node];
    int start = row_ptr[node];
    const size_t qoff = (size_t)sub * 16;   // byte offset within row

    for (int base = 0; base < d; base += 32) {
        int cnt = min(d - base, 32);
        int sidx = 0;
        if (lane < cnt) sidx = csr[start + base + lane];
        int iters = (cnt + EPI - 1) / EPI;

        int  i   = eslot;
        bool act = i < cnt;
        int  s   = __shfl_sync(0xffffffffu, sidx, i & 31);
        uint4 qv = make_uint4(0u, 0u, 0u, 0u);
        if (act) qv = *(const uint4*)(Q + (size_t)s * FEAT + qoff);

        for (int it = 1; it <= iters; it++) {
            int  i2   = it * EPI + eslot;
            bool act2 = i2 < cnt;
            int  s2   = __shfl_sync(0xffffffffu, sidx, i2 & 31);
            uint4 qn  = make_uint4(0u, 0u, 0u, 0u);
            if (act2) qn = *(const uint4*)(Q + (size_t)s2 * FEAT + qoff);
            if (act) {
                const uint32_t* w = &qv.x;
                #pragma unroll
                for (int j = 0; j < 4; j++) {
                    __half2 qlo = e4m3x2_to_h2((uint16_t)w[j]);
                    __half2 qhi = e4m3x2_to_h2((uint16_t)(w[j] >> 16));
                    a[2*j]   = h2add(a[2*j],   __hfma2_relu(qlo, one, p[2*j]));
                    a[2*j+1] = h2add(a[2*j+1], __hfma2_relu(qhi, one, p[2*j+1]));
                }
            }
            qv = qn; act = act2;
        }
    }

    // reduce accumulators across edge slots
    #pragma unroll
    for (int off = LPR; off < 32; off <<= 1) {
        #pragma unroll
        for (int j = 0; j < 8; j++) {
            uint32_t u = __shfl_xor_sync(0xffffffffu, *(uint32_t*)&a[j], off);
            a[j] = h2add(a[j], *(__half2*)&u);
        }
    }

    if (eslot == 0) {
        float inv = 1.0f / (float)(d > 0 ? d : 1);
        uint4 o0, o1;
        uint32_t* ow = &o0.x;
        #pragma unroll
        for (int j = 0; j < 8; j++) {
            float2 f = __half22float2(a[j]);
            __half2 h = __floats2half2_rn(f.x * inv, f.y * inv);
            if (j < 4) ow[j] = *(uint32_t*)&h;
            else       (&o1.x)[j - 4] = *(uint32_t*)&h;
        }
        *(uint4*)(S + foff)     = o0;
        *(uint4*)(S + foff + 8) = o1;
    }
}

// ---------------------------------------------------------------------------
// Actor head
// ---------------------------------------------------------------------------
__global__ __launch_bounds__(256) void head_kernel(
    const float* __restrict__ state,
    const float* __restrict__ gsum, const int* __restrict__ gcnt,
    const float* __restrict__ fc1_w, const float* __restrict__ fc1_b,
    const float* __restrict__ fc2_w, const float* __restrict__ fc2_b,
    const float* __restrict__ mean_w, const float* __restrict__ mean_b,
    const float* __restrict__ ls_w, const float* __restrict__ ls_b,
    float* __restrict__ out, int n_graphs)
{
    __shared__ float z[128];
    __shared__ float h1[256];
    __shared__ float h2[256];
    int b = blockIdx.x;
    int t = threadIdx.x;
    if (b >= n_graphs) return;

    if (t < 64) {
        z[t] = state[b * 64 + t];
    } else if (t < 128) {
        float c = fmaxf((float)gcnt[b], 1.f);
        z[t] = gsum[b * GNN_DIM + (t - 64)] / c;
    }
    __syncthreads();

    {
        float s = fc1_b[t];
        #pragma unroll 4
        for (int k = 0; k < 128; k++) s += z[k] * fc1_w[k * 256 + t];
        h1[t] = fmaxf(s, 0.f);
    }
    __syncthreads();
    {
        float s = fc2_b[t];
        #pragma unroll 4
        for (int k = 0; k < 256; k++) s += h1[k] * fc2_w[k * 256 + t];
        h2[t] = fmaxf(s, 0.f);
    }
    __syncthreads();

    if (t < ACTION_DIM) {
        float s = mean_b[t];
        #pragma unroll 4
        for (int k = 0; k < 256; k++) s += h2[k] * mean_w[k * ACTION_DIM + t];
        out[b * ACTION_DIM + t] = s;
    } else if (t < 2 * ACTION_DIM) {
        int j = t - ACTION_DIM;
        float s = ls_b[j];
        #pragma unroll 4
        for (int k = 0; k < 256; k++) s += h2[k] * ls_w[k * ACTION_DIM + j];
        s = fminf(fmaxf(s, -20.f), 2.f);
        out[n_graphs * ACTION_DIM + b * ACTION_DIM + j] = s;
    }
}

// ---------------------------------------------------------------------------
// Launch (R10 structure: CSR side fork only, single main chain)
// ---------------------------------------------------------------------------
extern "C" void kernel_launch(void* const* d_in, const int* in_sizes, int n_in,
                              void* d_out, int out_size)
{
    const float* state  = (const float*)d_in[0];
    const float* x      = (const float*)d_in[1];
    const int*   eidx   = (const int*)  d_in[2];
    const int*   nbatch = (const int*)  d_in[3];
    const float* g1w1   = (const float*)d_in[4];
    const float* g1b1   = (const float*)d_in[5];
    const float* g1w2   = (const float*)d_in[6];
    const float* g1b2   = (const float*)d_in[7];
    const float* g2w1   = (const float*)d_in[8];
    const float* g2b1   = (const float*)d_in[9];
    const float* g2w2   = (const float*)d_in[10];
    const float* g2b2   = (const float*)d_in[11];
    const float* fc1_w  = (const float*)d_in[12];
    const float* fc1_b  = (const float*)d_in[13];
    const float* fc2_w  = (const float*)d_in[14];
    const float* fc2_b  = (const float*)d_in[15];
    const float* mean_w = (const float*)d_in[16];
    const float* mean_b = (const float*)d_in[17];
    const float* ls_w   = (const float*)d_in[18];
    const float* ls_b   = (const float*)d_in[19];
    float* out = (float*)d_out;

    const int n_graphs = in_sizes[0] / 64;
    const int n_nodes  = in_sizes[1] / NODE_DIM;
    const int n_edges  = in_sizes[2] / 2;
    const int* e_src = eidx;
    const int* e_dst = eidx + n_edges;

    __half *bufXh, *bufPh, *bufSh;
    uint8_t *bufQ8;
    float *gsum;
    int *deg, *cursor, *rowptr, *csr, *gcnt, *agg, *flag;
    cudaGetSymbolAddress((void**)&bufXh,  g_bufXh);
    cudaGetSymbolAddress((void**)&bufPh,  g_bufPh);
    cudaGetSymbolAddress((void**)&bufQ8,  g_bufQ8);
    cudaGetSymbolAddress((void**)&bufSh,  g_bufSh);
    cudaGetSymbolAddress((void**)&deg,    g_deg);
    cudaGetSymbolAddress((void**)&cursor, g_cursor);
    cudaGetSymbolAddress((void**)&rowptr, g_rowptr);
    cudaGetSymbolAddress((void**)&csr,    g_csr);
    cudaGetSymbolAddress((void**)&agg,    g_agg);
    cudaGetSymbolAddress((void**)&flag,   g_flag);
    cudaGetSymbolAddress((void**)&gsum,   g_gsum);
    cudaGetSymbolAddress((void**)&gcnt,   g_gcnt);

    static cudaStream_t s_side = nullptr;
    static cudaEvent_t  s_ev0 = nullptr, s_ev1 = nullptr;
    if (!s_side) {
        cudaStreamCreateWithFlags(&s_side, cudaStreamNonBlocking);
        cudaEventCreateWithFlags(&s_ev0, cudaEventDisableTiming);
        cudaEventCreateWithFlags(&s_ev1, cudaEventDisableTiming);
    }

    const int ncvt = n_nodes * NODE_DIM / 4;
    const int mb = (n_nodes + 127) / 128;
    const int eblocks  = (n_edges + 255) / 256;
    const int e4blocks = (n_edges / 4 + 256) / 256;
    const int sblocks  = (n_nodes + SCAN_BLK - 1) / SCAN_BLK;
    const int gblocks  = (n_nodes * 32 + 255) / 256;   // one warp per node

    // ---- zero first (both chains depend on it), then fork ----
    zero_side_kernel<<<(n_nodes + 255) / 256, 256>>>(deg, gcnt, flag, n_nodes, n_graphs);
    cudaEventRecord(s_ev0, 0);
    cudaStreamWaitEvent(s_side, s_ev0, 0);

    // ---- side stream: CSR chain ----
    hist_count4_kernel<<<e4blocks, 256, 0, s_side>>>(e_dst, deg, nbatch, gcnt, n_edges, n_nodes);
    scan_lb_kernel<<<sblocks, SCAN_BLK, 0, s_side>>>(deg, rowptr, cursor, agg, flag, n_nodes);
    fill_kernel<<<eblocks, 256, 0, s_side>>>(e_src, e_dst, cursor, csr, n_edges);
    cudaEventRecord(s_ev1, s_side);

    // ---- main stream: x cvt + L1 P/Q GEMM (independent of CSR) ----
    init_main_kernel<<<(ncvt + 255) / 256, 256>>>(x, bufXh, gsum, n_graphs, ncvt);
    gemm_pq<<<dim3(mb, 2), 256>>>(bufXh, g1w1, g1w1 + 64 * 128, g1b1,
                                  bufPh, bufQ8, n_nodes, 128, 128);

    // ---- join ----
    cudaStreamWaitEvent(0, s_ev1, 0);

    gather16_fp8_kernel<8><<<gblocks, 256>>>(bufPh, bufQ8, rowptr, deg, csr, bufSh, n_nodes);
    gemm_h1pq2<<<mb, 256>>>(bufSh, g1w2, g1b2, g2w1, g2b1, deg,
                            bufPh, bufQ8, n_nodes);
    gather16_fp8_kernel<4><<<gblocks, 256>>>(bufPh, bufQ8, rowptr, deg, csr, bufSh, n_nodes);
    gemm_h2pool<<<mb, 256>>>(bufSh, g2w2, g2b2, deg, nbatch, gsum, n_nodes);
    head_kernel<<<n_graphs, 256>>>(state, gsum, gcnt,
                                   fc1_w, fc1_b, fc2_w, fc2_b,
                                   mean_w, mean_b, ls_w, ls_b,
                                   out, n_graphs);
}